// round 9
// baseline (speedup 1.0000x reference)
#include <cuda_runtime.h>
#include <cuda_bf16.h>
#include <math.h>
#include <stdint.h>

#define B_      4
#define L_      2048
#define DMODEL  1024
#define DINNER  2048
#define DSTATE  64
#define KCONV   4
#define MTOT    (B_*L_)     // 8192
#define NOUT    128         // 2*DSTATE (x_ssm | dt)
#define CTSPLIT 16
#define ESPLIT  4
#define H4N     512         // 4*NOUT rows of Eall

// ---------------- scratch (device globals: no allocation allowed) ----------
__device__ float g_const[4*NOUT];
__device__ float g_Ctp[CTSPLIT*DMODEL*DSTATE];
__device__ __align__(16) __nv_bfloat16 g_Cthi[DMODEL*DSTATE];
__device__ __align__(16) __nv_bfloat16 g_Ctlo[DMODEL*DSTATE];
__device__ float g_Ep[ESPLIT*H4N*DMODEL];
__device__ __align__(16) __nv_bfloat16 g_Ehi[H4N*DMODEL];
__device__ __align__(16) __nv_bfloat16 g_Elo[H4N*DMODEL];
__device__ __align__(16) __nv_bfloat16 g_Abhi[H4N*DINNER];
__device__ __align__(16) __nv_bfloat16 g_Ablo[H4N*DINNER];
__device__ __align__(16) __nv_bfloat16 g_WThi[DMODEL*DINNER];
__device__ __align__(16) __nv_bfloat16 g_WTlo[DMODEL*DINNER];
__device__ __align__(16) __nv_bfloat16 g_Xhi[(size_t)MTOT*DMODEL];
__device__ __align__(16) __nv_bfloat16 g_Xlo[(size_t)MTOT*DMODEL];
__device__ __align__(16) __nv_bfloat16 g_zThi[B_*DSTATE*L_];
__device__ __align__(16) __nv_bfloat16 g_zTlo[B_*DSTATE*L_];
__device__ __align__(16) __nv_bfloat16 g_zhi[MTOT*DSTATE];
__device__ __align__(16) __nv_bfloat16 g_zlo[MTOT*DSTATE];
__device__ __align__(16) float g_H4[(size_t)MTOT*H4N];
__device__ float g_dA[B_*DSTATE*L_];
__device__ float g_dBx[B_*DSTATE*L_];

// ======================= helpers ===========================================
__device__ __forceinline__ uint32_t smem_u32(const void* p){
    uint32_t a;
    asm("{ .reg .u64 t; cvta.to.shared.u64 t, %1; cvt.u32.u64 %0, t; }" : "=r"(a) : "l"(p));
    return a;
}
__device__ __forceinline__ void cp16(uint32_t saddr, const void* g){
    asm volatile("cp.async.ca.shared.global [%0], [%1], 16;" :: "r"(saddr), "l"(g));
}
__device__ __forceinline__ void cp_commit(){ asm volatile("cp.async.commit_group;"); }
__device__ __forceinline__ void cp_wait0(){ asm volatile("cp.async.wait_group 0;"); }
__device__ __forceinline__ void cp_wait1(){ asm volatile("cp.async.wait_group 1;"); }

__device__ __forceinline__ void ldsm4(uint32_t* r, uint32_t addr){
    asm volatile("ldmatrix.sync.aligned.m8n8.x4.shared.b16 {%0,%1,%2,%3}, [%4];"
        : "=r"(r[0]), "=r"(r[1]), "=r"(r[2]), "=r"(r[3]) : "r"(addr));
}
__device__ __forceinline__ void mma16816(float* d, const uint32_t* a, uint32_t b0, uint32_t b1){
    asm volatile("mma.sync.aligned.m16n8k16.row.col.f32.bf16.bf16.f32 "
        "{%0,%1,%2,%3}, {%4,%5,%6,%7}, {%8,%9}, {%0,%1,%2,%3};"
        : "+f"(d[0]), "+f"(d[1]), "+f"(d[2]), "+f"(d[3])
        : "r"(a[0]), "r"(a[1]), "r"(a[2]), "r"(a[3]), "r"(b0), "r"(b1));
}
__device__ __forceinline__ void bf_split(float v, __nv_bfloat16& h, __nv_bfloat16& l){
    h = __float2bfloat16(v);
    l = __float2bfloat16(v - __bfloat162float(h));
}

// ======================= fused prep mega-kernel ============================
// Role by blockIdx.x:
//  [0,4096)        absplit       (Abig -> bf16 hi/lo)
//  [4096,6144)     wT            (Win transpose -> bf16 hi/lo)
//  [6144,14336)    xsplit        (x -> bf16 hi/lo)
//  [14336,14848)   const
//  [14848,15104)   ct_split      (SIMT split-K GEMM partials)
#define PREP_BLOCKS (4096 + 2048 + 8192 + 512 + 256)

__global__ __launch_bounds__(256)
void prep_all(const float* __restrict__ x,    const float* __restrict__ Win,
              const float* __restrict__ convw, const float* __restrict__ convb,
              const float* __restrict__ Wx,   const float* __restrict__ b_x,
              const float* __restrict__ Wdt,  const float* __restrict__ b_dt,
              const float* __restrict__ b_in,
              const float* __restrict__ Wout, const float* __restrict__ Dmat){
    __shared__ __align__(16) char sh[8448];
    const int blk = blockIdx.x;
    const int tid = threadIdx.x;

    if (blk < 4096){
        // ---- absplit
        int idx = blk*256 + tid;
        int c   = idx & (DINNER-1);
        int row = idx >> 11;
        int k4  = row >> 7, j = row & 127;
        float p = (j < DSTATE) ? Wx[j*DINNER + c] : Wdt[(j-DSTATE)*DINNER + c];
        float v = p * convw[c*KCONV + k4];
        __nv_bfloat16 h, l; bf_split(v, h, l);
        g_Abhi[idx] = h; g_Ablo[idx] = l;
    } else if (blk < 6144){
        // ---- wT (Win [c][dm] -> [dm][c] hi/lo)
        float (*t)[33] = (float(*)[33])sh;
        int b  = blk - 4096;
        int n0 = (b & 31)*32;
        int k0 = (b >> 5)*32;
        int tx = tid & 31, ty = tid >> 5;
        #pragma unroll
        for (int p = 0; p < 4; p++){
            int k = ty + p*8;
            t[k][tx] = Win[(size_t)(k0+k)*DMODEL + n0 + tx];
        }
        __syncthreads();
        #pragma unroll
        for (int p = 0; p < 4; p++){
            int n = ty + p*8;
            float v = t[tx][n];
            __nv_bfloat16 h, l; bf_split(v, h, l);
            size_t o = (size_t)(n0+n)*DINNER + k0 + tx;
            g_WThi[o] = h; g_WTlo[o] = l;
        }
    } else if (blk < 14336){
        // ---- xsplit
        int i = (blk - 6144)*256 + tid;
        float4 v = *(const float4*)&x[(size_t)i*4];
        __nv_bfloat16 h0,h1,h2,h3,l0,l1,l2,l3;
        bf_split(v.x,h0,l0); bf_split(v.y,h1,l1); bf_split(v.z,h2,l2); bf_split(v.w,h3,l3);
        __nv_bfloat162 hp0 = __halves2bfloat162(h0,h1), hp1 = __halves2bfloat162(h2,h3);
        __nv_bfloat162 lp0 = __halves2bfloat162(l0,l1), lp1 = __halves2bfloat162(l2,l3);
        uint2 hu, lu;
        hu.x = *reinterpret_cast<uint32_t*>(&hp0); hu.y = *reinterpret_cast<uint32_t*>(&hp1);
        lu.x = *reinterpret_cast<uint32_t*>(&lp0); lu.y = *reinterpret_cast<uint32_t*>(&lp1);
        *(uint2*)&g_Xhi[(size_t)i*4] = hu;
        *(uint2*)&g_Xlo[(size_t)i*4] = lu;
    } else if (blk < 14848){
        // ---- const
        float* red = (float*)sh;
        int b  = blk - 14336;
        int j  = b & 127;
        int lp = b >> 7;
        int kstart = 3 - lp;
        float partial = 0.f;
        for (int c = tid; c < DINNER; c += 256){
            float sw = 0.f;
            #pragma unroll
            for (int k = 0; k < 4; k++) if (k >= kstart) sw += convw[c*4 + k];
            float p = (j < DSTATE) ? Wx[j*DINNER + c] : Wdt[(j-DSTATE)*DINNER + c];
            partial += p * (convb[c] + b_in[c]*sw);
        }
        red[tid] = partial; __syncthreads();
        for (int s = 128; s > 0; s >>= 1){ if (tid < s) red[tid] += red[tid+s]; __syncthreads(); }
        if (tid == 0){
            float bias = (j < DSTATE) ? b_x[j] : b_dt[j-DSTATE];
            g_const[lp*NOUT + j] = red[0] + bias;
        }
    } else {
        // ---- ct_split (BM=BN=64, BK=16, TM=TN=4)
        float (*As)[65] = (float(*)[65])sh;                 // 16*65*4 = 4160 B
        float (*Bs)[65] = (float(*)[65])(sh + 4224);        // +4160 (pad to 4224)
        int b  = blk - 14848;
        int m0 = (b & 15)*64;
        int z  = b >> 4;
        int kbase = z * (DINNER/CTSPLIT);
        int tx = tid & 15, ty = tid >> 4;
        float acc[4][4];
        #pragma unroll
        for (int a=0;a<4;a++)
            #pragma unroll
            for (int c=0;c<4;c++) acc[a][c] = 0.f;

        for (int kk = 0; kk < DINNER/CTSPLIT; kk += 16){
            #pragma unroll
            for (int idx = tid; idx < 64*16; idx += 256){
                int m = idx >> 4, kq = idx & 15;
                As[kq][m] = Wout[(size_t)(m0+m)*DINNER + kbase + kk + kq];
            }
            #pragma unroll
            for (int idx = tid; idx < 64*16; idx += 256){
                int n = idx >> 4, kq = idx & 15;
                Bs[kq][n] = Dmat[(size_t)n*DINNER + kbase + kk + kq];
            }
            __syncthreads();
            #pragma unroll
            for (int i = 0; i < 16; i++){
                float af[4], bf[4];
                #pragma unroll
                for (int t2=0;t2<4;t2++) af[t2] = As[i][ty*4+t2];
                #pragma unroll
                for (int t2=0;t2<4;t2++) bf[t2] = Bs[i][tx*4+t2];
                #pragma unroll
                for (int a=0;a<4;a++)
                    #pragma unroll
                    for (int c=0;c<4;c++) acc[a][c] += af[a]*bf[c];
            }
            __syncthreads();
        }
        float* outp = g_Ctp + (size_t)z*DMODEL*DSTATE;
        #pragma unroll
        for (int a=0;a<4;a++)
            #pragma unroll
            for (int c=0;c<4;c++)
                outp[(size_t)(m0+ty*4+a)*DSTATE + tx*4 + c] = acc[a][c];
    }
}

// ======================= fused reduce kernel ===============================
// [0,2048): reduce_E ; [2048,2304): reduce_ct
__global__ __launch_bounds__(256)
void reduce_all(){
    const int blk = blockIdx.x;
    const int tid = threadIdx.x;
    if (blk < 2048){
        int i = blk*256 + tid;
        float s = 0.f;
        #pragma unroll
        for (int z = 0; z < ESPLIT; z++) s += g_Ep[(size_t)z*H4N*DMODEL + i];
        __nv_bfloat16 h, l; bf_split(s, h, l);
        g_Ehi[i] = h; g_Elo[i] = l;
    } else {
        int i = (blk - 2048)*256 + tid;
        float s = 0.f;
        #pragma unroll
        for (int z = 0; z < CTSPLIT; z++) s += g_Ctp[(size_t)z*DMODEL*DSTATE + i];
        __nv_bfloat16 h, l; bf_split(s, h, l);
        g_Cthi[i] = h; g_Ctlo[i] = l;
    }
}

// ======================= unified fused-pass mma.sync GEMM ==================
// C = A @ B^T, bf16 hi/lo (3 MMA groups per K-tile), fp32 accum.
// BM=BN=128, BK=32, 8 warps (64x32). 3-stage cp.async pipeline, 120KB smem.
#define MG_PITCH 80
#define MG_TILE  (128*MG_PITCH)       // 10240 B
#define MG_STG   (4*MG_TILE)          // 40960 B per stage
#define MG_SMEM  (3*MG_STG)           // 122880 B

__device__ __forceinline__ void mg_issue4(uint32_t base,
        const __nv_bfloat16* __restrict__ Ah, const __nv_bfloat16* __restrict__ Al,
        const __nv_bfloat16* __restrict__ Bh, const __nv_bfloat16* __restrict__ Bl,
        int m0, int n0, int lda, int ldb, int kk, int tid){
    #pragma unroll
    for (int i = tid; i < 512; i += 256){
        int r = i >> 2, c = i & 3;
        uint32_t o = r*MG_PITCH + c*16;
        size_t ga = (size_t)(m0 + r)*lda + kk + c*8;
        size_t gb = (size_t)(n0 + r)*ldb + kk + c*8;
        cp16(base +             o, Ah + ga);
        cp16(base + MG_TILE   + o, Al + ga);
        cp16(base + 2*MG_TILE + o, Bh + gb);
        cp16(base + 3*MG_TILE + o, Bl + gb);
    }
    cp_commit();
}

template<int MODE>
__global__ __launch_bounds__(256)
void mma_gemm(const __nv_bfloat16* __restrict__ Ahi, const __nv_bfloat16* __restrict__ Alo,
              const __nv_bfloat16* __restrict__ Bhi, const __nv_bfloat16* __restrict__ Blo,
              float* __restrict__ C, const float* __restrict__ bias,
              int lda, int ldb, int kLen, int ldc, size_t sliceStride){
    extern __shared__ __align__(16) char dsm[];
    const int tid  = threadIdx.x;
    const int wid  = tid >> 5, lane = tid & 31;
    const int m0   = blockIdx.x * 128;
    const int n0   = blockIdx.y * 128;
    const int kbase= blockIdx.z * kLen;
    const int wm   = (wid >> 2) * 64;
    const int wn   = (wid & 3) * 32;
    const uint32_t sbu = smem_u32(dsm);
    const int NIT = kLen >> 5;          // >= 2 for all our shapes

    float acc[4][4][4];
    #pragma unroll
    for (int a=0;a<4;a++)
        #pragma unroll
        for (int b=0;b<4;b++)
            #pragma unroll
            for (int c=0;c<4;c++) acc[a][b][c] = 0.f;

    // prologue: 2 stages in flight
    mg_issue4(sbu,          Ahi, Alo, Bhi, Blo, m0, n0, lda, ldb, kbase,      tid);
    mg_issue4(sbu + MG_STG, Ahi, Alo, Bhi, Blo, m0, n0, lda, ldb, kbase + 32, tid);

    for (int t = 0; t < NIT; t++){
        if (t + 1 < NIT) cp_wait1(); else cp_wait0();
        __syncthreads();
        if (t + 2 < NIT)
            mg_issue4(sbu + ((t+2)%3)*MG_STG, Ahi, Alo, Bhi, Blo,
                      m0, n0, lda, ldb, kbase + (t+2)*32, tid);

        const uint32_t sb = sbu + (t%3)*MG_STG;
        #pragma unroll
        for (int ks = 0; ks < 2; ks++){
            uint32_t ah[4][4], al[4][4], bh[2][4], bl[2][4];
            #pragma unroll
            for (int mb = 0; mb < 4; mb++){
                int row = wm + mb*16 + (lane & 15);
                uint32_t o = row*MG_PITCH + ks*32 + (lane >> 4)*16;
                ldsm4(ah[mb], sb + o);
                ldsm4(al[mb], sb + MG_TILE + o);
            }
            #pragma unroll
            for (int nb2 = 0; nb2 < 2; nb2++){
                int row = wn + nb2*16 + ((lane >> 3) & 1)*8 + (lane & 7);
                uint32_t o = row*MG_PITCH + ks*32 + (lane >> 4)*16;
                ldsm4(bh[nb2], sb + 2*MG_TILE + o);
                ldsm4(bl[nb2], sb + 3*MG_TILE + o);
            }
            #pragma unroll
            for (int mb = 0; mb < 4; mb++)
                #pragma unroll
                for (int nb = 0; nb < 4; nb++){
                    int nb2 = nb >> 1, odd = nb & 1;
                    mma16816(acc[mb][nb], ah[mb], bh[nb2][odd?1:0], bh[nb2][odd?3:2]);
                }
            #pragma unroll
            for (int mb = 0; mb < 4; mb++)
                #pragma unroll
                for (int nb = 0; nb < 4; nb++){
                    int nb2 = nb >> 1, odd = nb & 1;
                    mma16816(acc[mb][nb], ah[mb], bl[nb2][odd?1:0], bl[nb2][odd?3:2]);
                }
            #pragma unroll
            for (int mb = 0; mb < 4; mb++)
                #pragma unroll
                for (int nb = 0; nb < 4; nb++){
                    int nb2 = nb >> 1, odd = nb & 1;
                    mma16816(acc[mb][nb], al[mb], bh[nb2][odd?1:0], bh[nb2][odd?3:2]);
                }
        }
    }

    float* Co = (MODE == 2) ? (C + (size_t)blockIdx.z*sliceStride) : C;
    #pragma unroll
    for (int mb = 0; mb < 4; mb++){
        #pragma unroll
        for (int nb = 0; nb < 4; nb++){
            int r = m0 + wm + mb*16 + (lane >> 2);
            int c = n0 + wn + nb*8 + (lane & 3)*2;
            float2 v0 = make_float2(acc[mb][nb][0], acc[mb][nb][1]);
            float2 v1 = make_float2(acc[mb][nb][2], acc[mb][nb][3]);
            if (MODE == 0 && bias){
                float b0 = bias[c], b1 = bias[c+1];
                v0.x += b0; v0.y += b1;
                v1.x += b0; v1.y += b1;
            }
            *(float2*)&Co[(size_t)r*ldc + c]       = v0;
            *(float2*)&Co[(size_t)(r+8)*ldc + c]   = v1;
        }
    }
}

// ======================= combine (shift-sum + SSM param) ===================
__global__ __launch_bounds__(256)
void combine(const float* __restrict__ A_log){
    const int tid = threadIdx.x;
    const int m0  = blockIdx.x * 64;
    __shared__ float sG[64*130];
    #pragma unroll
    for (int it = 0; it < 32; it++){
        int i = tid + it*256;
        int r = i >> 7, j = i & 127;
        int m = m0 + r, l = m & (L_-1);
        int lp = l < 3 ? l : 3;
        float v = g_const[lp*NOUT + j];
        int kmin = (l >= 3) ? 0 : (3 - l);
        #pragma unroll
        for (int k = 0; k < 4; k++)
            if (k >= kmin) v += g_H4[(size_t)(m-3+k)*H4N + k*128 + j];
        sG[r*130 + j] = v;
    }
    __syncthreads();
    #pragma unroll
    for (int it = 0; it < 16; it++){
        int p = tid + it*256;
        int s = p >> 6;
        int r = p & 63;
        float xs = sG[r*130 + s];
        float dv = sG[r*130 + 64 + s];
        float dt = dv > 20.f ? dv : log1pf(expf(dv));
        float Aa = -expf(A_log[s]);
        float dA = expf(Aa*dt);
        float dBx = (1.f - dA)/Aa * xs;
        int m = m0 + r;
        int b = m >> 11;
        int l = m & (L_-1);
        size_t o = ((size_t)(b*DSTATE + s))*L_ + l;
        g_dA[o]  = dA;
        g_dBx[o] = dBx;
    }
}

// ======================= scan (coalesced zT output) ========================
__global__ __launch_bounds__(256)
void scan_kernel(){
    const int bs = blockIdx.x;
    const int t  = threadIdx.x;
    const size_t base = (size_t)bs * L_;
    float a[8], bb[8];
    #pragma unroll
    for (int i=0;i<8;i++){ a[i] = g_dA[base + t*8 + i]; bb[i] = g_dBx[base + t*8 + i]; }

    float Ai = 1.f, Bi = 0.f;
    #pragma unroll
    for (int i=0;i<8;i++){ Bi = Bi*a[i] + bb[i]; Ai *= a[i]; }

    const unsigned lane = t & 31, wid = t >> 5;
    #pragma unroll
    for (int off = 1; off < 32; off <<= 1){
        float Au = __shfl_up_sync(0xffffffffu, Ai, off);
        float Bu = __shfl_up_sync(0xffffffffu, Bi, off);
        if (lane >= off){ Bi = Ai*Bu + Bi; Ai = Ai*Au; }
    }
    __shared__ float wA[8], wB[8], pB[8];
    if (lane == 31){ wA[wid] = Ai; wB[wid] = Bi; }
    __syncthreads();
    if (t == 0){
        float cB = 0.f;
        #pragma unroll
        for (int w = 0; w < 8; w++){
            pB[w] = cB;
            cB = cB*wA[w] + wB[w];
        }
    }
    __syncthreads();
    float eA = __shfl_up_sync(0xffffffffu, Ai, 1);
    float eB = __shfl_up_sync(0xffffffffu, Bi, 1);
    if (lane == 0){ eA = 1.f; eB = 0.f; }
    float z = eA*pB[wid] + eB;

    __nv_bfloat16 hb[8], lb[8];
    #pragma unroll
    for (int i = 0; i < 8; i++){
        z = a[i]*z + bb[i];
        bf_split(z, hb[i], lb[i]);
    }
    *(uint4*)&g_zThi[base + t*8] = *(uint4*)hb;
    *(uint4*)&g_zTlo[base + t*8] = *(uint4*)lb;
}

// zT [b*64+s][l] -> z [m][s] (64x64 smem tiles, hi+lo)
__global__ __launch_bounds__(256)
void transpose_z(){
    __shared__ __nv_bfloat16 th[64][66];
    __shared__ __nv_bfloat16 tl[64][66];
    const int tid = threadIdx.x;
    const int l0  = blockIdx.x * 64;
    const int b   = blockIdx.y;
    #pragma unroll
    for (int it = 0; it < 16; it++){
        int i = tid + it*256;
        int s = i >> 6, lo = i & 63;
        size_t o = (size_t)(b*DSTATE + s)*L_ + l0 + lo;
        th[s][lo] = g_zThi[o];
        tl[s][lo] = g_zTlo[o];
    }
    __syncthreads();
    #pragma unroll
    for (int it = 0; it < 16; it++){
        int i = tid + it*256;
        int l = i >> 6, s = i & 63;
        size_t o = (size_t)(b*L_ + l0 + l)*DSTATE + s;
        g_zhi[o] = th[s][l];
        g_zlo[o] = tl[s][l];
    }
}

// ======================= launch ============================================
extern "C" void kernel_launch(void* const* d_in, const int* in_sizes, int n_in,
                              void* d_out, int out_size){
    const float* x      = (const float*)d_in[0];
    const float* W_in   = (const float*)d_in[1];
    const float* b_in   = (const float*)d_in[2];
    const float* conv_w = (const float*)d_in[3];
    const float* conv_b = (const float*)d_in[4];
    const float* W_x    = (const float*)d_in[5];
    const float* b_x    = (const float*)d_in[6];
    const float* W_dt   = (const float*)d_in[7];
    const float* b_dt   = (const float*)d_in[8];
    const float* A_log  = (const float*)d_in[9];
    const float* D_mat  = (const float*)d_in[10];
    const float* W_out  = (const float*)d_in[11];
    const float* b_out  = (const float*)d_in[12];
    float* out = (float*)d_out;

    cudaFuncSetAttribute(mma_gemm<0>, cudaFuncAttributeMaxDynamicSharedMemorySize, MG_SMEM);
    cudaFuncSetAttribute(mma_gemm<2>, cudaFuncAttributeMaxDynamicSharedMemorySize, MG_SMEM);

    float *pEp, *pH4;
    cudaGetSymbolAddress((void**)&pEp, g_Ep);
    cudaGetSymbolAddress((void**)&pH4, g_H4);
    __nv_bfloat16 *pAbh, *pAbl, *pWTh, *pWTl, *pEh, *pEl, *pXh, *pXl, *pZh, *pZl, *pCth, *pCtl;
    cudaGetSymbolAddress((void**)&pAbh, g_Abhi);
    cudaGetSymbolAddress((void**)&pAbl, g_Ablo);
    cudaGetSymbolAddress((void**)&pWTh, g_WThi);
    cudaGetSymbolAddress((void**)&pWTl, g_WTlo);
    cudaGetSymbolAddress((void**)&pEh,  g_Ehi);
    cudaGetSymbolAddress((void**)&pEl,  g_Elo);
    cudaGetSymbolAddress((void**)&pXh,  g_Xhi);
    cudaGetSymbolAddress((void**)&pXl,  g_Xlo);
    cudaGetSymbolAddress((void**)&pZh,  g_zhi);
    cudaGetSymbolAddress((void**)&pZl,  g_zlo);
    cudaGetSymbolAddress((void**)&pCth, g_Cthi);
    cudaGetSymbolAddress((void**)&pCtl, g_Ctlo);

    // 1. all independent prep + ct GEMM in one wave
    prep_all<<<PREP_BLOCKS, 256>>>(x, W_in, conv_w, conv_b,
                                   W_x, b_x, W_dt, b_dt, b_in, W_out, D_mat);

    // 2. E = Abig @ Win (tensor cores, split-K=4)
    mma_gemm<2><<<dim3(H4N/128, DMODEL/128, ESPLIT), 256, MG_SMEM>>>(
        pAbh, pAbl, pWTh, pWTl, pEp, nullptr,
        DINNER, DINNER, DINNER/ESPLIT, DMODEL, (size_t)H4N*DMODEL);

    // 3. reduce_E + reduce_ct fused
    reduce_all<<<2048 + 256, 256>>>();

    // 4. H4 = X @ Eall^T
    mma_gemm<0><<<dim3(MTOT/128, H4N/128, 1), 256, MG_SMEM>>>(
        pXh, pXl, pEh, pEl, pH4, nullptr,
        DMODEL, DMODEL, DMODEL, H4N, 0);

    // 5-7. combine, scan, transpose
    combine<<<MTOT/64, 256>>>(A_log);
    scan_kernel<<<B_*DSTATE, 256>>>();
    transpose_z<<<dim3(L_/64, B_), 256>>>();

    // 8. out = z @ Ct^T + b_out
    mma_gemm<0><<<dim3(MTOT/128, DMODEL/128, 1), 256, MG_SMEM>>>(
        pZh, pZl, pCth, pCtl, out, b_out,
        DSTATE, DSTATE, DSTATE, DMODEL, 0);
}

// round 10
// speedup vs baseline: 1.0200x; 1.0200x over previous
#include <cuda_runtime.h>
#include <cuda_bf16.h>
#include <math.h>
#include <stdint.h>

#define B_      4
#define L_      2048
#define DMODEL  1024
#define DINNER  2048
#define DSTATE  64
#define KCONV   4
#define MTOT    (B_*L_)     // 8192
#define NOUT    128         // 2*DSTATE (x_ssm | dt)
#define CTSPLIT 16
#define ESPLIT  4
#define H4N     512         // 4*NOUT rows of Eall

// ---------------- scratch (device globals: no allocation allowed) ----------
__device__ float g_const[4*NOUT];
__device__ float g_Ctp[CTSPLIT*DMODEL*DSTATE];
__device__ __align__(16) __nv_bfloat16 g_Cthi[DMODEL*DSTATE];
__device__ __align__(16) __nv_bfloat16 g_Ctlo[DMODEL*DSTATE];
__device__ float g_Ep[ESPLIT*H4N*DMODEL];
__device__ __align__(16) __nv_bfloat16 g_Ehi[H4N*DMODEL];
__device__ __align__(16) __nv_bfloat16 g_Elo[H4N*DMODEL];
__device__ __align__(16) __nv_bfloat16 g_Abhi[H4N*DINNER];
__device__ __align__(16) __nv_bfloat16 g_Ablo[H4N*DINNER];
__device__ __align__(16) __nv_bfloat16 g_WThi[DMODEL*DINNER];
__device__ __align__(16) __nv_bfloat16 g_WTlo[DMODEL*DINNER];
__device__ __align__(16) __nv_bfloat16 g_Xhi[(size_t)MTOT*DMODEL];
__device__ __align__(16) __nv_bfloat16 g_Xlo[(size_t)MTOT*DMODEL];
__device__ __align__(16) __nv_bfloat16 g_zThi[B_*DSTATE*L_];
__device__ __align__(16) __nv_bfloat16 g_zTlo[B_*DSTATE*L_];
__device__ __align__(16) __nv_bfloat16 g_zhi[MTOT*DSTATE];
__device__ __align__(16) __nv_bfloat16 g_zlo[MTOT*DSTATE];
__device__ __align__(16) float g_H4[(size_t)MTOT*H4N];
__device__ float g_dA[B_*DSTATE*L_];
__device__ float g_dBx[B_*DSTATE*L_];

// ======================= helpers ===========================================
__device__ __forceinline__ uint32_t smem_u32(const void* p){
    uint32_t a;
    asm("{ .reg .u64 t; cvta.to.shared.u64 t, %1; cvt.u32.u64 %0, t; }" : "=r"(a) : "l"(p));
    return a;
}
__device__ __forceinline__ void cp16(uint32_t saddr, const void* g){
    asm volatile("cp.async.ca.shared.global [%0], [%1], 16;" :: "r"(saddr), "l"(g));
}
__device__ __forceinline__ void cp_commit(){ asm volatile("cp.async.commit_group;"); }
__device__ __forceinline__ void cp_wait0(){ asm volatile("cp.async.wait_group 0;"); }

__device__ __forceinline__ void ldsm4(uint32_t* r, uint32_t addr){
    asm volatile("ldmatrix.sync.aligned.m8n8.x4.shared.b16 {%0,%1,%2,%3}, [%4];"
        : "=r"(r[0]), "=r"(r[1]), "=r"(r[2]), "=r"(r[3]) : "r"(addr));
}
__device__ __forceinline__ void mma16816(float* d, const uint32_t* a, uint32_t b0, uint32_t b1){
    asm volatile("mma.sync.aligned.m16n8k16.row.col.f32.bf16.bf16.f32 "
        "{%0,%1,%2,%3}, {%4,%5,%6,%7}, {%8,%9}, {%0,%1,%2,%3};"
        : "+f"(d[0]), "+f"(d[1]), "+f"(d[2]), "+f"(d[3])
        : "r"(a[0]), "r"(a[1]), "r"(a[2]), "r"(a[3]), "r"(b0), "r"(b1));
}
__device__ __forceinline__ void bf_split(float v, __nv_bfloat16& h, __nv_bfloat16& l){
    h = __float2bfloat16(v);
    l = __float2bfloat16(v - __bfloat162float(h));
}

// ======================= fused prep mega-kernel ============================
// Role by blockIdx.x:
//  [0,4096)        absplit       (Abig -> bf16 hi/lo)
//  [4096,6144)     wT            (Win transpose -> bf16 hi/lo)
//  [6144,14336)    xsplit        (x -> bf16 hi/lo)
//  [14336,14848)   const
//  [14848,15104)   ct_split      (SIMT split-K GEMM partials)
#define PREP_BLOCKS (4096 + 2048 + 8192 + 512 + 256)

__global__ __launch_bounds__(256)
void prep_all(const float* __restrict__ x,    const float* __restrict__ Win,
              const float* __restrict__ convw, const float* __restrict__ convb,
              const float* __restrict__ Wx,   const float* __restrict__ b_x,
              const float* __restrict__ Wdt,  const float* __restrict__ b_dt,
              const float* __restrict__ b_in,
              const float* __restrict__ Wout, const float* __restrict__ Dmat){
    __shared__ __align__(16) char sh[8448];
    const int blk = blockIdx.x;
    const int tid = threadIdx.x;

    if (blk < 4096){
        // ---- absplit
        int idx = blk*256 + tid;
        int c   = idx & (DINNER-1);
        int row = idx >> 11;
        int k4  = row >> 7, j = row & 127;
        float p = (j < DSTATE) ? Wx[j*DINNER + c] : Wdt[(j-DSTATE)*DINNER + c];
        float v = p * convw[c*KCONV + k4];
        __nv_bfloat16 h, l; bf_split(v, h, l);
        g_Abhi[idx] = h; g_Ablo[idx] = l;
    } else if (blk < 6144){
        // ---- wT (Win [c][dm] -> [dm][c] hi/lo)
        float (*t)[33] = (float(*)[33])sh;
        int b  = blk - 4096;
        int n0 = (b & 31)*32;
        int k0 = (b >> 5)*32;
        int tx = tid & 31, ty = tid >> 5;
        #pragma unroll
        for (int p = 0; p < 4; p++){
            int k = ty + p*8;
            t[k][tx] = Win[(size_t)(k0+k)*DMODEL + n0 + tx];
        }
        __syncthreads();
        #pragma unroll
        for (int p = 0; p < 4; p++){
            int n = ty + p*8;
            float v = t[tx][n];
            __nv_bfloat16 h, l; bf_split(v, h, l);
            size_t o = (size_t)(n0+n)*DINNER + k0 + tx;
            g_WThi[o] = h; g_WTlo[o] = l;
        }
    } else if (blk < 14336){
        // ---- xsplit
        int i = (blk - 6144)*256 + tid;
        float4 v = *(const float4*)&x[(size_t)i*4];
        __nv_bfloat16 h0,h1,h2,h3,l0,l1,l2,l3;
        bf_split(v.x,h0,l0); bf_split(v.y,h1,l1); bf_split(v.z,h2,l2); bf_split(v.w,h3,l3);
        __nv_bfloat162 hp0 = __halves2bfloat162(h0,h1), hp1 = __halves2bfloat162(h2,h3);
        __nv_bfloat162 lp0 = __halves2bfloat162(l0,l1), lp1 = __halves2bfloat162(l2,l3);
        uint2 hu, lu;
        hu.x = *reinterpret_cast<uint32_t*>(&hp0); hu.y = *reinterpret_cast<uint32_t*>(&hp1);
        lu.x = *reinterpret_cast<uint32_t*>(&lp0); lu.y = *reinterpret_cast<uint32_t*>(&lp1);
        *(uint2*)&g_Xhi[(size_t)i*4] = hu;
        *(uint2*)&g_Xlo[(size_t)i*4] = lu;
    } else if (blk < 14848){
        // ---- const
        float* red = (float*)sh;
        int b  = blk - 14336;
        int j  = b & 127;
        int lp = b >> 7;
        int kstart = 3 - lp;
        float partial = 0.f;
        for (int c = tid; c < DINNER; c += 256){
            float sw = 0.f;
            #pragma unroll
            for (int k = 0; k < 4; k++) if (k >= kstart) sw += convw[c*4 + k];
            float p = (j < DSTATE) ? Wx[j*DINNER + c] : Wdt[(j-DSTATE)*DINNER + c];
            partial += p * (convb[c] + b_in[c]*sw);
        }
        red[tid] = partial; __syncthreads();
        for (int s = 128; s > 0; s >>= 1){ if (tid < s) red[tid] += red[tid+s]; __syncthreads(); }
        if (tid == 0){
            float bias = (j < DSTATE) ? b_x[j] : b_dt[j-DSTATE];
            g_const[lp*NOUT + j] = red[0] + bias;
        }
    } else {
        // ---- ct_split (BM=BN=64, BK=16, TM=TN=4)
        float (*As)[65] = (float(*)[65])sh;                 // 16*65*4 = 4160 B
        float (*Bs)[65] = (float(*)[65])(sh + 4224);
        int b  = blk - 14848;
        int m0 = (b & 15)*64;
        int z  = b >> 4;
        int kbase = z * (DINNER/CTSPLIT);
        int tx = tid & 15, ty = tid >> 4;
        float acc[4][4];
        #pragma unroll
        for (int a=0;a<4;a++)
            #pragma unroll
            for (int c=0;c<4;c++) acc[a][c] = 0.f;

        for (int kk = 0; kk < DINNER/CTSPLIT; kk += 16){
            #pragma unroll
            for (int idx = tid; idx < 64*16; idx += 256){
                int m = idx >> 4, kq = idx & 15;
                As[kq][m] = Wout[(size_t)(m0+m)*DINNER + kbase + kk + kq];
            }
            #pragma unroll
            for (int idx = tid; idx < 64*16; idx += 256){
                int n = idx >> 4, kq = idx & 15;
                Bs[kq][n] = Dmat[(size_t)n*DINNER + kbase + kk + kq];
            }
            __syncthreads();
            #pragma unroll
            for (int i = 0; i < 16; i++){
                float af[4], bf[4];
                #pragma unroll
                for (int t2=0;t2<4;t2++) af[t2] = As[i][ty*4+t2];
                #pragma unroll
                for (int t2=0;t2<4;t2++) bf[t2] = Bs[i][tx*4+t2];
                #pragma unroll
                for (int a=0;a<4;a++)
                    #pragma unroll
                    for (int c=0;c<4;c++) acc[a][c] += af[a]*bf[c];
            }
            __syncthreads();
        }
        float* outp = g_Ctp + (size_t)z*DMODEL*DSTATE;
        #pragma unroll
        for (int a=0;a<4;a++)
            #pragma unroll
            for (int c=0;c<4;c++)
                outp[(size_t)(m0+ty*4+a)*DSTATE + tx*4 + c] = acc[a][c];
    }
}

// ======================= fused reduce kernel ===============================
// [0,2048): reduce_E ; [2048,2304): reduce_ct
__global__ __launch_bounds__(256)
void reduce_all(){
    const int blk = blockIdx.x;
    const int tid = threadIdx.x;
    if (blk < 2048){
        int i = blk*256 + tid;
        float s = 0.f;
        #pragma unroll
        for (int z = 0; z < ESPLIT; z++) s += g_Ep[(size_t)z*H4N*DMODEL + i];
        __nv_bfloat16 h, l; bf_split(s, h, l);
        g_Ehi[i] = h; g_Elo[i] = l;
    } else {
        int i = (blk - 2048)*256 + tid;
        float s = 0.f;
        #pragma unroll
        for (int z = 0; z < CTSPLIT; z++) s += g_Ctp[(size_t)z*DMODEL*DSTATE + i];
        __nv_bfloat16 h, l; bf_split(s, h, l);
        g_Cthi[i] = h; g_Ctlo[i] = l;
    }
}

// ======================= unified fused-pass mma.sync GEMM ==================
// C = A @ B^T, bf16 hi/lo (3 MMA groups per K-tile), fp32 accum.
// BM=BN=128, BK=32, 8 warps (64x32). 2-stage double buffer, 80KB smem,
// 2 CTAs/SM (one wave for grid<=296).
#define MG_PITCH 80
#define MG_TILE  (128*MG_PITCH)       // 10240 B
#define MG_STG   (4*MG_TILE)          // 40960 B per stage
#define MG_SMEM  (2*MG_STG)           // 81920 B

__device__ __forceinline__ void mg_issue4(uint32_t base,
        const __nv_bfloat16* __restrict__ Ah, const __nv_bfloat16* __restrict__ Al,
        const __nv_bfloat16* __restrict__ Bh, const __nv_bfloat16* __restrict__ Bl,
        int m0, int n0, int lda, int ldb, int kk, int tid){
    #pragma unroll
    for (int i = tid; i < 512; i += 256){
        int r = i >> 2, c = i & 3;
        uint32_t o = r*MG_PITCH + c*16;
        size_t ga = (size_t)(m0 + r)*lda + kk + c*8;
        size_t gb = (size_t)(n0 + r)*ldb + kk + c*8;
        cp16(base +             o, Ah + ga);
        cp16(base + MG_TILE   + o, Al + ga);
        cp16(base + 2*MG_TILE + o, Bh + gb);
        cp16(base + 3*MG_TILE + o, Bl + gb);
    }
    cp_commit();
}

template<int MODE>
__global__ __launch_bounds__(256, 2)
void mma_gemm(const __nv_bfloat16* __restrict__ Ahi, const __nv_bfloat16* __restrict__ Alo,
              const __nv_bfloat16* __restrict__ Bhi, const __nv_bfloat16* __restrict__ Blo,
              float* __restrict__ C, const float* __restrict__ bias,
              int lda, int ldb, int kLen, int ldc, size_t sliceStride){
    extern __shared__ __align__(16) char dsm[];
    const int tid  = threadIdx.x;
    const int wid  = tid >> 5, lane = tid & 31;
    const int m0   = blockIdx.x * 128;
    const int n0   = blockIdx.y * 128;
    const int kbase= blockIdx.z * kLen;
    const int wm   = (wid >> 2) * 64;
    const int wn   = (wid & 3) * 32;
    const uint32_t sbu = smem_u32(dsm);
    const int NIT = kLen >> 5;

    float acc[4][4][4];
    #pragma unroll
    for (int a=0;a<4;a++)
        #pragma unroll
        for (int b=0;b<4;b++)
            #pragma unroll
            for (int c=0;c<4;c++) acc[a][b][c] = 0.f;

    mg_issue4(sbu, Ahi, Alo, Bhi, Blo, m0, n0, lda, ldb, kbase, tid);
    cp_wait0();
    __syncthreads();

    for (int t = 0; t < NIT; t++){
        int buf = t & 1;
        if (t + 1 < NIT)
            mg_issue4(sbu + (buf^1)*MG_STG, Ahi, Alo, Bhi, Blo,
                      m0, n0, lda, ldb, kbase + (t+1)*32, tid);

        const uint32_t sb = sbu + buf*MG_STG;
        #pragma unroll
        for (int ks = 0; ks < 2; ks++){
            uint32_t ah[4][4], al[4][4], bh[2][4], bl[2][4];
            #pragma unroll
            for (int mb = 0; mb < 4; mb++){
                int row = wm + mb*16 + (lane & 15);
                uint32_t o = row*MG_PITCH + ks*32 + (lane >> 4)*16;
                ldsm4(ah[mb], sb + o);
                ldsm4(al[mb], sb + MG_TILE + o);
            }
            #pragma unroll
            for (int nb2 = 0; nb2 < 2; nb2++){
                int row = wn + nb2*16 + ((lane >> 3) & 1)*8 + (lane & 7);
                uint32_t o = row*MG_PITCH + ks*32 + (lane >> 4)*16;
                ldsm4(bh[nb2], sb + 2*MG_TILE + o);
                ldsm4(bl[nb2], sb + 3*MG_TILE + o);
            }
            #pragma unroll
            for (int mb = 0; mb < 4; mb++)
                #pragma unroll
                for (int nb = 0; nb < 4; nb++){
                    int nb2 = nb >> 1, odd = nb & 1;
                    mma16816(acc[mb][nb], ah[mb], bh[nb2][odd?1:0], bh[nb2][odd?3:2]);
                }
            #pragma unroll
            for (int mb = 0; mb < 4; mb++)
                #pragma unroll
                for (int nb = 0; nb < 4; nb++){
                    int nb2 = nb >> 1, odd = nb & 1;
                    mma16816(acc[mb][nb], ah[mb], bl[nb2][odd?1:0], bl[nb2][odd?3:2]);
                }
            #pragma unroll
            for (int mb = 0; mb < 4; mb++)
                #pragma unroll
                for (int nb = 0; nb < 4; nb++){
                    int nb2 = nb >> 1, odd = nb & 1;
                    mma16816(acc[mb][nb], al[mb], bh[nb2][odd?1:0], bh[nb2][odd?3:2]);
                }
        }

        if (t + 1 < NIT){ cp_wait0(); __syncthreads(); }
    }

    float* Co = (MODE == 2) ? (C + (size_t)blockIdx.z*sliceStride) : C;
    #pragma unroll
    for (int mb = 0; mb < 4; mb++){
        #pragma unroll
        for (int nb = 0; nb < 4; nb++){
            int r = m0 + wm + mb*16 + (lane >> 2);
            int c = n0 + wn + nb*8 + (lane & 3)*2;
            float2 v0 = make_float2(acc[mb][nb][0], acc[mb][nb][1]);
            float2 v1 = make_float2(acc[mb][nb][2], acc[mb][nb][3]);
            if (MODE == 0 && bias){
                float b0 = bias[c], b1 = bias[c+1];
                v0.x += b0; v0.y += b1;
                v1.x += b0; v1.y += b1;
            }
            *(float2*)&Co[(size_t)r*ldc + c]       = v0;
            *(float2*)&Co[(size_t)(r+8)*ldc + c]   = v1;
        }
    }
}

// ======================= combine (shift-sum + SSM param) ===================
__global__ __launch_bounds__(256)
void combine(const float* __restrict__ A_log){
    const int tid = threadIdx.x;
    const int m0  = blockIdx.x * 64;
    __shared__ float sG[64*130];
    #pragma unroll
    for (int it = 0; it < 32; it++){
        int i = tid + it*256;
        int r = i >> 7, j = i & 127;
        int m = m0 + r, l = m & (L_-1);
        int lp = l < 3 ? l : 3;
        float v = g_const[lp*NOUT + j];
        int kmin = (l >= 3) ? 0 : (3 - l);
        #pragma unroll
        for (int k = 0; k < 4; k++)
            if (k >= kmin) v += g_H4[(size_t)(m-3+k)*H4N + k*128 + j];
        sG[r*130 + j] = v;
    }
    __syncthreads();
    #pragma unroll
    for (int it = 0; it < 16; it++){
        int p = tid + it*256;
        int s = p >> 6;
        int r = p & 63;
        float xs = sG[r*130 + s];
        float dv = sG[r*130 + 64 + s];
        float dt = dv > 20.f ? dv : log1pf(expf(dv));
        float Aa = -expf(A_log[s]);
        float dA = expf(Aa*dt);
        float dBx = (1.f - dA)/Aa * xs;
        int m = m0 + r;
        int b = m >> 11;
        int l = m & (L_-1);
        size_t o = ((size_t)(b*DSTATE + s))*L_ + l;
        g_dA[o]  = dA;
        g_dBx[o] = dBx;
    }
}

// ======================= scan (coalesced zT output) ========================
__global__ __launch_bounds__(256)
void scan_kernel(){
    const int bs = blockIdx.x;
    const int t  = threadIdx.x;
    const size_t base = (size_t)bs * L_;
    float a[8], bb[8];
    #pragma unroll
    for (int i=0;i<8;i++){ a[i] = g_dA[base + t*8 + i]; bb[i] = g_dBx[base + t*8 + i]; }

    float Ai = 1.f, Bi = 0.f;
    #pragma unroll
    for (int i=0;i<8;i++){ Bi = Bi*a[i] + bb[i]; Ai *= a[i]; }

    const unsigned lane = t & 31, wid = t >> 5;
    #pragma unroll
    for (int off = 1; off < 32; off <<= 1){
        float Au = __shfl_up_sync(0xffffffffu, Ai, off);
        float Bu = __shfl_up_sync(0xffffffffu, Bi, off);
        if (lane >= off){ Bi = Ai*Bu + Bi; Ai = Ai*Au; }
    }
    __shared__ float wA[8], wB[8], pB[8];
    if (lane == 31){ wA[wid] = Ai; wB[wid] = Bi; }
    __syncthreads();
    if (t == 0){
        float cB = 0.f;
        #pragma unroll
        for (int w = 0; w < 8; w++){
            pB[w] = cB;
            cB = cB*wA[w] + wB[w];
        }
    }
    __syncthreads();
    float eA = __shfl_up_sync(0xffffffffu, Ai, 1);
    float eB = __shfl_up_sync(0xffffffffu, Bi, 1);
    if (lane == 0){ eA = 1.f; eB = 0.f; }
    float z = eA*pB[wid] + eB;

    __nv_bfloat16 hb[8], lb[8];
    #pragma unroll
    for (int i = 0; i < 8; i++){
        z = a[i]*z + bb[i];
        bf_split(z, hb[i], lb[i]);
    }
    *(uint4*)&g_zThi[base + t*8] = *(uint4*)hb;
    *(uint4*)&g_zTlo[base + t*8] = *(uint4*)lb;
}

// zT [b*64+s][l] -> z [m][s] (64x64 smem tiles, hi+lo)
__global__ __launch_bounds__(256)
void transpose_z(){
    __shared__ __nv_bfloat16 th[64][66];
    __shared__ __nv_bfloat16 tl[64][66];
    const int tid = threadIdx.x;
    const int l0  = blockIdx.x * 64;
    const int b   = blockIdx.y;
    #pragma unroll
    for (int it = 0; it < 16; it++){
        int i = tid + it*256;
        int s = i >> 6, lo = i & 63;
        size_t o = (size_t)(b*DSTATE + s)*L_ + l0 + lo;
        th[s][lo] = g_zThi[o];
        tl[s][lo] = g_zTlo[o];
    }
    __syncthreads();
    #pragma unroll
    for (int it = 0; it < 16; it++){
        int i = tid + it*256;
        int l = i >> 6, s = i & 63;
        size_t o = (size_t)(b*L_ + l0 + l)*DSTATE + s;
        g_zhi[o] = th[s][l];
        g_zlo[o] = tl[s][l];
    }
}

// ======================= launch ============================================
extern "C" void kernel_launch(void* const* d_in, const int* in_sizes, int n_in,
                              void* d_out, int out_size){
    const float* x      = (const float*)d_in[0];
    const float* W_in   = (const float*)d_in[1];
    const float* b_in   = (const float*)d_in[2];
    const float* conv_w = (const float*)d_in[3];
    const float* conv_b = (const float*)d_in[4];
    const float* W_x    = (const float*)d_in[5];
    const float* b_x    = (const float*)d_in[6];
    const float* W_dt   = (const float*)d_in[7];
    const float* b_dt   = (const float*)d_in[8];
    const float* A_log  = (const float*)d_in[9];
    const float* D_mat  = (const float*)d_in[10];
    const float* W_out  = (const float*)d_in[11];
    const float* b_out  = (const float*)d_in[12];
    float* out = (float*)d_out;

    cudaFuncSetAttribute(mma_gemm<0>, cudaFuncAttributeMaxDynamicSharedMemorySize, MG_SMEM);
    cudaFuncSetAttribute(mma_gemm<2>, cudaFuncAttributeMaxDynamicSharedMemorySize, MG_SMEM);

    float *pEp, *pH4;
    cudaGetSymbolAddress((void**)&pEp, g_Ep);
    cudaGetSymbolAddress((void**)&pH4, g_H4);
    __nv_bfloat16 *pAbh, *pAbl, *pWTh, *pWTl, *pEh, *pEl, *pXh, *pXl, *pZh, *pZl, *pCth, *pCtl;
    cudaGetSymbolAddress((void**)&pAbh, g_Abhi);
    cudaGetSymbolAddress((void**)&pAbl, g_Ablo);
    cudaGetSymbolAddress((void**)&pWTh, g_WThi);
    cudaGetSymbolAddress((void**)&pWTl, g_WTlo);
    cudaGetSymbolAddress((void**)&pEh,  g_Ehi);
    cudaGetSymbolAddress((void**)&pEl,  g_Elo);
    cudaGetSymbolAddress((void**)&pXh,  g_Xhi);
    cudaGetSymbolAddress((void**)&pXl,  g_Xlo);
    cudaGetSymbolAddress((void**)&pZh,  g_zhi);
    cudaGetSymbolAddress((void**)&pZl,  g_zlo);
    cudaGetSymbolAddress((void**)&pCth, g_Cthi);
    cudaGetSymbolAddress((void**)&pCtl, g_Ctlo);

    // 1. all independent prep + ct GEMM in one wave
    prep_all<<<PREP_BLOCKS, 256>>>(x, W_in, conv_w, conv_b,
                                   W_x, b_x, W_dt, b_dt, b_in, W_out, D_mat);

    // 2. E = Abig @ Win (tensor cores, split-K=4)
    mma_gemm<2><<<dim3(H4N/128, DMODEL/128, ESPLIT), 256, MG_SMEM>>>(
        pAbh, pAbl, pWTh, pWTl, pEp, nullptr,
        DINNER, DINNER, DINNER/ESPLIT, DMODEL, (size_t)H4N*DMODEL);

    // 3. reduce_E + reduce_ct fused
    reduce_all<<<2048 + 256, 256>>>();

    // 4. H4 = X @ Eall^T
    mma_gemm<0><<<dim3(MTOT/128, H4N/128, 1), 256, MG_SMEM>>>(
        pXh, pXl, pEh, pEl, pH4, nullptr,
        DMODEL, DMODEL, DMODEL, H4N, 0);

    // 5-7. combine, scan, transpose
    combine<<<MTOT/64, 256>>>(A_log);
    scan_kernel<<<B_*DSTATE, 256>>>();
    transpose_z<<<dim3(L_/64, B_), 256>>>();

    // 8. out = z @ Ct^T + b_out
    mma_gemm<0><<<dim3(MTOT/128, DMODEL/128, 1), 256, MG_SMEM>>>(
        pZh, pZl, pCth, pCtl, out, b_out,
        DSTATE, DSTATE, DSTATE, DMODEL, 0);
}

// round 11
// speedup vs baseline: 1.2463x; 1.2219x over previous
#include <cuda_runtime.h>
#include <cuda_bf16.h>
#include <cuda_fp16.h>
#include <math.h>
#include <stdint.h>

#define B_      4
#define L_      2048
#define DMODEL  1024
#define DINNER  2048
#define DSTATE  64
#define KCONV   4
#define MTOT    (B_*L_)     // 8192
#define NOUT    128         // 2*DSTATE (x_ssm | dt)
#define CTSPLIT 16
#define ESPLIT  4
#define H4N     512         // 4*NOUT rows of Eall
#define ESCALE      4096.0f
#define INV_ESCALE  2.44140625e-4f

// ---------------- scratch (device globals: no allocation allowed) ----------
__device__ float g_const[4*NOUT];
__device__ float g_Ctp[CTSPLIT*DMODEL*DSTATE];
__device__ __align__(16) __nv_bfloat16 g_Cthi[DMODEL*DSTATE];
__device__ __align__(16) __nv_bfloat16 g_Ctlo[DMODEL*DSTATE];
__device__ float g_Ep[ESPLIT*H4N*DMODEL];
__device__ __align__(16) __half g_Ehf[H4N*DMODEL];            // fp16 E*4096 hi
__device__ __align__(16) __half g_Elf[H4N*DMODEL];            // fp16 E*4096 lo
__device__ __align__(16) __nv_bfloat16 g_Abhi[H4N*DINNER];
__device__ __align__(16) __nv_bfloat16 g_Ablo[H4N*DINNER];
__device__ __align__(16) __nv_bfloat16 g_WThi[DMODEL*DINNER];
__device__ __align__(16) __nv_bfloat16 g_WTlo[DMODEL*DINNER];
__device__ __align__(16) __half g_Xh[(size_t)MTOT*DMODEL];    // fp16(x)
__device__ __align__(16) __nv_bfloat16 g_zThi[B_*DSTATE*L_];
__device__ __align__(16) __nv_bfloat16 g_zTlo[B_*DSTATE*L_];
__device__ __align__(16) __nv_bfloat16 g_zhi[MTOT*DSTATE];
__device__ __align__(16) __nv_bfloat16 g_zlo[MTOT*DSTATE];
__device__ __align__(16) float g_H4[(size_t)MTOT*H4N];
__device__ float g_dA[B_*DSTATE*L_];
__device__ float g_dBx[B_*DSTATE*L_];

// ======================= helpers ===========================================
__device__ __forceinline__ uint32_t smem_u32(const void* p){
    uint32_t a;
    asm("{ .reg .u64 t; cvta.to.shared.u64 t, %1; cvt.u32.u64 %0, t; }" : "=r"(a) : "l"(p));
    return a;
}
__device__ __forceinline__ void cp16(uint32_t saddr, const void* g){
    asm volatile("cp.async.ca.shared.global [%0], [%1], 16;" :: "r"(saddr), "l"(g));
}
__device__ __forceinline__ void cp_commit(){ asm volatile("cp.async.commit_group;"); }
__device__ __forceinline__ void cp_wait0(){ asm volatile("cp.async.wait_group 0;"); }

__device__ __forceinline__ void ldsm4(uint32_t* r, uint32_t addr){
    asm volatile("ldmatrix.sync.aligned.m8n8.x4.shared.b16 {%0,%1,%2,%3}, [%4];"
        : "=r"(r[0]), "=r"(r[1]), "=r"(r[2]), "=r"(r[3]) : "r"(addr));
}
__device__ __forceinline__ void mma16816(float* d, const uint32_t* a, uint32_t b0, uint32_t b1){
    asm volatile("mma.sync.aligned.m16n8k16.row.col.f32.bf16.bf16.f32 "
        "{%0,%1,%2,%3}, {%4,%5,%6,%7}, {%8,%9}, {%0,%1,%2,%3};"
        : "+f"(d[0]), "+f"(d[1]), "+f"(d[2]), "+f"(d[3])
        : "r"(a[0]), "r"(a[1]), "r"(a[2]), "r"(a[3]), "r"(b0), "r"(b1));
}
__device__ __forceinline__ void mma16816h(float* d, const uint32_t* a, uint32_t b0, uint32_t b1){
    asm volatile("mma.sync.aligned.m16n8k16.row.col.f32.f16.f16.f32 "
        "{%0,%1,%2,%3}, {%4,%5,%6,%7}, {%8,%9}, {%0,%1,%2,%3};"
        : "+f"(d[0]), "+f"(d[1]), "+f"(d[2]), "+f"(d[3])
        : "r"(a[0]), "r"(a[1]), "r"(a[2]), "r"(a[3]), "r"(b0), "r"(b1));
}
__device__ __forceinline__ void bf_split(float v, __nv_bfloat16& h, __nv_bfloat16& l){
    h = __float2bfloat16(v);
    l = __float2bfloat16(v - __bfloat162float(h));
}

// ======================= fused prep mega-kernel ============================
// Roles: [0,4096) absplit | [4096,6144) wT | [6144,10240) xsplit(fp16)
//        [10240,10752) const | [10752,11008) ct_split
#define PREP_BLOCKS (4096 + 2048 + 4096 + 512 + 256)

__global__ __launch_bounds__(256)
void prep_all(const float* __restrict__ x,    const float* __restrict__ Win,
              const float* __restrict__ convw, const float* __restrict__ convb,
              const float* __restrict__ Wx,   const float* __restrict__ b_x,
              const float* __restrict__ Wdt,  const float* __restrict__ b_dt,
              const float* __restrict__ b_in,
              const float* __restrict__ Wout, const float* __restrict__ Dmat){
    __shared__ __align__(16) char sh[8448];
    const int blk = blockIdx.x;
    const int tid = threadIdx.x;

    if (blk < 4096){
        // ---- absplit (bf16 hi/lo)
        int idx = blk*256 + tid;
        int c   = idx & (DINNER-1);
        int row = idx >> 11;
        int k4  = row >> 7, j = row & 127;
        float p = (j < DSTATE) ? Wx[j*DINNER + c] : Wdt[(j-DSTATE)*DINNER + c];
        float v = p * convw[c*KCONV + k4];
        __nv_bfloat16 h, l; bf_split(v, h, l);
        g_Abhi[idx] = h; g_Ablo[idx] = l;
    } else if (blk < 6144){
        // ---- wT (Win [c][dm] -> [dm][c] bf16 hi/lo)
        float (*t)[33] = (float(*)[33])sh;
        int b  = blk - 4096;
        int n0 = (b & 31)*32;
        int k0 = (b >> 5)*32;
        int tx = tid & 31, ty = tid >> 5;
        #pragma unroll
        for (int p = 0; p < 4; p++){
            int k = ty + p*8;
            t[k][tx] = Win[(size_t)(k0+k)*DMODEL + n0 + tx];
        }
        __syncthreads();
        #pragma unroll
        for (int p = 0; p < 4; p++){
            int n = ty + p*8;
            float v = t[tx][n];
            __nv_bfloat16 h, l; bf_split(v, h, l);
            size_t o = (size_t)(n0+n)*DINNER + k0 + tx;
            g_WThi[o] = h; g_WTlo[o] = l;
        }
    } else if (blk < 10240){
        // ---- xsplit: fp16 single (8 floats per thread)
        size_t i = ((size_t)(blk - 6144)*256 + tid)*8;
        float4 v0 = *(const float4*)&x[i];
        float4 v1 = *(const float4*)&x[i+4];
        __half h[8];
        h[0]=__float2half(v0.x); h[1]=__float2half(v0.y);
        h[2]=__float2half(v0.z); h[3]=__float2half(v0.w);
        h[4]=__float2half(v1.x); h[5]=__float2half(v1.y);
        h[6]=__float2half(v1.z); h[7]=__float2half(v1.w);
        *(uint4*)&g_Xh[i] = *(uint4*)h;
    } else if (blk < 10752){
        // ---- const
        float* red = (float*)sh;
        int b  = blk - 10240;
        int j  = b & 127;
        int lp = b >> 7;
        int kstart = 3 - lp;
        float partial = 0.f;
        for (int c = tid; c < DINNER; c += 256){
            float sw = 0.f;
            #pragma unroll
            for (int k = 0; k < 4; k++) if (k >= kstart) sw += convw[c*4 + k];
            float p = (j < DSTATE) ? Wx[j*DINNER + c] : Wdt[(j-DSTATE)*DINNER + c];
            partial += p * (convb[c] + b_in[c]*sw);
        }
        red[tid] = partial; __syncthreads();
        for (int s = 128; s > 0; s >>= 1){ if (tid < s) red[tid] += red[tid+s]; __syncthreads(); }
        if (tid == 0){
            float bias = (j < DSTATE) ? b_x[j] : b_dt[j-DSTATE];
            g_const[lp*NOUT + j] = red[0] + bias;
        }
    } else {
        // ---- ct_split
        float (*As)[65] = (float(*)[65])sh;
        float (*Bs)[65] = (float(*)[65])(sh + 4224);
        int b  = blk - 10752;
        int m0 = (b & 15)*64;
        int z  = b >> 4;
        int kbase = z * (DINNER/CTSPLIT);
        int tx = tid & 15, ty = tid >> 4;
        float acc[4][4];
        #pragma unroll
        for (int a=0;a<4;a++)
            #pragma unroll
            for (int c=0;c<4;c++) acc[a][c] = 0.f;

        for (int kk = 0; kk < DINNER/CTSPLIT; kk += 16){
            #pragma unroll
            for (int idx = tid; idx < 64*16; idx += 256){
                int m = idx >> 4, kq = idx & 15;
                As[kq][m] = Wout[(size_t)(m0+m)*DINNER + kbase + kk + kq];
            }
            #pragma unroll
            for (int idx = tid; idx < 64*16; idx += 256){
                int n = idx >> 4, kq = idx & 15;
                Bs[kq][n] = Dmat[(size_t)n*DINNER + kbase + kk + kq];
            }
            __syncthreads();
            #pragma unroll
            for (int i = 0; i < 16; i++){
                float af[4], bf[4];
                #pragma unroll
                for (int t2=0;t2<4;t2++) af[t2] = As[i][ty*4+t2];
                #pragma unroll
                for (int t2=0;t2<4;t2++) bf[t2] = Bs[i][tx*4+t2];
                #pragma unroll
                for (int a=0;a<4;a++)
                    #pragma unroll
                    for (int c=0;c<4;c++) acc[a][c] += af[a]*bf[c];
            }
            __syncthreads();
        }
        float* outp = g_Ctp + (size_t)z*DMODEL*DSTATE;
        #pragma unroll
        for (int a=0;a<4;a++)
            #pragma unroll
            for (int c=0;c<4;c++)
                outp[(size_t)(m0+ty*4+a)*DSTATE + tx*4 + c] = acc[a][c];
    }
}

// ======================= fused reduce kernel ===============================
// [0,2048): reduce_E (fp16 hi/lo, scaled x4096) ; [2048,2304): reduce_ct (bf16)
__global__ __launch_bounds__(256)
void reduce_all(){
    const int blk = blockIdx.x;
    const int tid = threadIdx.x;
    if (blk < 2048){
        int i = blk*256 + tid;
        float s = 0.f;
        #pragma unroll
        for (int z = 0; z < ESPLIT; z++) s += g_Ep[(size_t)z*H4N*DMODEL + i];
        float ss = s * ESCALE;
        __half h = __float2half(ss);
        __half l = __float2half(ss - __half2float(h));
        g_Ehf[i] = h; g_Elf[i] = l;
    } else {
        int i = (blk - 2048)*256 + tid;
        float s = 0.f;
        #pragma unroll
        for (int z = 0; z < CTSPLIT; z++) s += g_Ctp[(size_t)z*DMODEL*DSTATE + i];
        __nv_bfloat16 h, l; bf_split(s, h, l);
        g_Cthi[i] = h; g_Ctlo[i] = l;
    }
}

// ======================= 3-pass bf16 mma GEMM (E, final) ===================
#define MG_PITCH 80
#define MG_TILE  (128*MG_PITCH)       // 10240 B
#define MG_STG   (4*MG_TILE)          // 40960 B per stage
#define MG_SMEM  (2*MG_STG)           // 81920 B

__device__ __forceinline__ void mg_issue4(uint32_t base,
        const __nv_bfloat16* __restrict__ Ah, const __nv_bfloat16* __restrict__ Al,
        const __nv_bfloat16* __restrict__ Bh, const __nv_bfloat16* __restrict__ Bl,
        int m0, int n0, int lda, int ldb, int kk, int tid){
    #pragma unroll
    for (int i = tid; i < 512; i += 256){
        int r = i >> 2, c = i & 3;
        uint32_t o = r*MG_PITCH + c*16;
        size_t ga = (size_t)(m0 + r)*lda + kk + c*8;
        size_t gb = (size_t)(n0 + r)*ldb + kk + c*8;
        cp16(base +             o, Ah + ga);
        cp16(base + MG_TILE   + o, Al + ga);
        cp16(base + 2*MG_TILE + o, Bh + gb);
        cp16(base + 3*MG_TILE + o, Bl + gb);
    }
    cp_commit();
}

template<int MODE>
__global__ __launch_bounds__(256, 2)
void mma_gemm(const __nv_bfloat16* __restrict__ Ahi, const __nv_bfloat16* __restrict__ Alo,
              const __nv_bfloat16* __restrict__ Bhi, const __nv_bfloat16* __restrict__ Blo,
              float* __restrict__ C, const float* __restrict__ bias,
              int lda, int ldb, int kLen, int ldc, size_t sliceStride, float outScale){
    extern __shared__ __align__(16) char dsm[];
    const int tid  = threadIdx.x;
    const int wid  = tid >> 5, lane = tid & 31;
    const int m0   = blockIdx.x * 128;
    const int n0   = blockIdx.y * 128;
    const int kbase= blockIdx.z * kLen;
    const int wm   = (wid >> 2) * 64;
    const int wn   = (wid & 3) * 32;
    const uint32_t sbu = smem_u32(dsm);
    const int NIT = kLen >> 5;

    float acc[4][4][4];
    #pragma unroll
    for (int a=0;a<4;a++)
        #pragma unroll
        for (int b=0;b<4;b++)
            #pragma unroll
            for (int c=0;c<4;c++) acc[a][b][c] = 0.f;

    mg_issue4(sbu, Ahi, Alo, Bhi, Blo, m0, n0, lda, ldb, kbase, tid);
    cp_wait0();
    __syncthreads();

    for (int t = 0; t < NIT; t++){
        int buf = t & 1;
        if (t + 1 < NIT)
            mg_issue4(sbu + (buf^1)*MG_STG, Ahi, Alo, Bhi, Blo,
                      m0, n0, lda, ldb, kbase + (t+1)*32, tid);

        const uint32_t sb = sbu + buf*MG_STG;
        #pragma unroll
        for (int ks = 0; ks < 2; ks++){
            uint32_t ah[4][4], al[4][4], bh[2][4], bl[2][4];
            #pragma unroll
            for (int mb = 0; mb < 4; mb++){
                int row = wm + mb*16 + (lane & 15);
                uint32_t o = row*MG_PITCH + ks*32 + (lane >> 4)*16;
                ldsm4(ah[mb], sb + o);
                ldsm4(al[mb], sb + MG_TILE + o);
            }
            #pragma unroll
            for (int nb2 = 0; nb2 < 2; nb2++){
                int row = wn + nb2*16 + ((lane >> 3) & 1)*8 + (lane & 7);
                uint32_t o = row*MG_PITCH + ks*32 + (lane >> 4)*16;
                ldsm4(bh[nb2], sb + 2*MG_TILE + o);
                ldsm4(bl[nb2], sb + 3*MG_TILE + o);
            }
            #pragma unroll
            for (int mb = 0; mb < 4; mb++)
                #pragma unroll
                for (int nb = 0; nb < 4; nb++){
                    int nb2 = nb >> 1, odd = nb & 1;
                    mma16816(acc[mb][nb], ah[mb], bh[nb2][odd?1:0], bh[nb2][odd?3:2]);
                }
            #pragma unroll
            for (int mb = 0; mb < 4; mb++)
                #pragma unroll
                for (int nb = 0; nb < 4; nb++){
                    int nb2 = nb >> 1, odd = nb & 1;
                    mma16816(acc[mb][nb], ah[mb], bl[nb2][odd?1:0], bl[nb2][odd?3:2]);
                }
            #pragma unroll
            for (int mb = 0; mb < 4; mb++)
                #pragma unroll
                for (int nb = 0; nb < 4; nb++){
                    int nb2 = nb >> 1, odd = nb & 1;
                    mma16816(acc[mb][nb], al[mb], bh[nb2][odd?1:0], bh[nb2][odd?3:2]);
                }
        }

        if (t + 1 < NIT){ cp_wait0(); __syncthreads(); }
    }

    float* Co = (MODE == 2) ? (C + (size_t)blockIdx.z*sliceStride) : C;
    #pragma unroll
    for (int mb = 0; mb < 4; mb++){
        #pragma unroll
        for (int nb = 0; nb < 4; nb++){
            int r = m0 + wm + mb*16 + (lane >> 2);
            int c = n0 + wn + nb*8 + (lane & 3)*2;
            float2 v0 = make_float2(acc[mb][nb][0]*outScale, acc[mb][nb][1]*outScale);
            float2 v1 = make_float2(acc[mb][nb][2]*outScale, acc[mb][nb][3]*outScale);
            if (MODE == 0 && bias){
                float b0 = bias[c], b1 = bias[c+1];
                v0.x += b0; v0.y += b1;
                v1.x += b0; v1.y += b1;
            }
            *(float2*)&Co[(size_t)r*ldc + c]       = v0;
            *(float2*)&Co[(size_t)(r+8)*ldc + c]   = v1;
        }
    }
}

// ======================= 2-pass fp16 H4 GEMM ===============================
// H4[8192,512] = fp16(X) @ (Ehf+Elf)^T  (values scaled x4096; combine descales)
// Tiles {A, Bh, Bl}: 3 x 10240 B per stage, 2 stages = 61440 B.
#define MH_STG  (3*MG_TILE)           // 30720
#define MH_SMEM (2*MH_STG)            // 61440

__device__ __forceinline__ void mh_issue3(uint32_t base, int m0, int n0, int kk, int tid){
    #pragma unroll
    for (int i = tid; i < 512; i += 256){
        int r = i >> 2, c = i & 3;
        uint32_t o = r*MG_PITCH + c*16;
        size_t ga = (size_t)(m0 + r)*DMODEL + kk + c*8;
        size_t gb = (size_t)(n0 + r)*DMODEL + kk + c*8;
        cp16(base +             o, g_Xh  + ga);
        cp16(base + MG_TILE   + o, g_Ehf + gb);
        cp16(base + 2*MG_TILE + o, g_Elf + gb);
    }
    cp_commit();
}

__global__ __launch_bounds__(256, 2)
void mma_h4f(){
    extern __shared__ __align__(16) char dsm[];
    const int tid  = threadIdx.x;
    const int wid  = tid >> 5, lane = tid & 31;
    const int m0   = blockIdx.x * 128;
    const int n0   = blockIdx.y * 128;
    const int wm   = (wid >> 2) * 64;
    const int wn   = (wid & 3) * 32;
    const uint32_t sbu = smem_u32(dsm);
    const int NIT = DMODEL/32;     // 32

    float acc[4][4][4];
    #pragma unroll
    for (int a=0;a<4;a++)
        #pragma unroll
        for (int b=0;b<4;b++)
            #pragma unroll
            for (int c=0;c<4;c++) acc[a][b][c] = 0.f;

    mh_issue3(sbu, m0, n0, 0, tid);
    cp_wait0();
    __syncthreads();

    for (int t = 0; t < NIT; t++){
        int buf = t & 1;
        if (t + 1 < NIT)
            mh_issue3(sbu + (buf^1)*MH_STG, m0, n0, (t+1)*32, tid);

        const uint32_t sb = sbu + buf*MH_STG;
        #pragma unroll
        for (int ks = 0; ks < 2; ks++){
            uint32_t ah[4][4], bh[2][4], bl[2][4];
            #pragma unroll
            for (int mb = 0; mb < 4; mb++){
                int row = wm + mb*16 + (lane & 15);
                uint32_t o = row*MG_PITCH + ks*32 + (lane >> 4)*16;
                ldsm4(ah[mb], sb + o);
            }
            #pragma unroll
            for (int nb2 = 0; nb2 < 2; nb2++){
                int row = wn + nb2*16 + ((lane >> 3) & 1)*8 + (lane & 7);
                uint32_t o = row*MG_PITCH + ks*32 + (lane >> 4)*16;
                ldsm4(bh[nb2], sb + MG_TILE + o);
                ldsm4(bl[nb2], sb + 2*MG_TILE + o);
            }
            #pragma unroll
            for (int mb = 0; mb < 4; mb++)
                #pragma unroll
                for (int nb = 0; nb < 4; nb++){
                    int nb2 = nb >> 1, odd = nb & 1;
                    mma16816h(acc[mb][nb], ah[mb], bh[nb2][odd?1:0], bh[nb2][odd?3:2]);
                }
            #pragma unroll
            for (int mb = 0; mb < 4; mb++)
                #pragma unroll
                for (int nb = 0; nb < 4; nb++){
                    int nb2 = nb >> 1, odd = nb & 1;
                    mma16816h(acc[mb][nb], ah[mb], bl[nb2][odd?1:0], bl[nb2][odd?3:2]);
                }
        }

        if (t + 1 < NIT){ cp_wait0(); __syncthreads(); }
    }

    #pragma unroll
    for (int mb = 0; mb < 4; mb++){
        #pragma unroll
        for (int nb = 0; nb < 4; nb++){
            int r = m0 + wm + mb*16 + (lane >> 2);
            int c = n0 + wn + nb*8 + (lane & 3)*2;
            *(float2*)&g_H4[(size_t)r*H4N + c]     = make_float2(acc[mb][nb][0], acc[mb][nb][1]);
            *(float2*)&g_H4[(size_t)(r+8)*H4N + c] = make_float2(acc[mb][nb][2], acc[mb][nb][3]);
        }
    }
}

// ======================= combine (descale + shift-sum + SSM param) =========
__global__ __launch_bounds__(256)
void combine(const float* __restrict__ A_log){
    const int tid = threadIdx.x;
    const int m0  = blockIdx.x * 64;
    __shared__ float sG[64*130];
    #pragma unroll
    for (int it = 0; it < 32; it++){
        int i = tid + it*256;
        int r = i >> 7, j = i & 127;
        int m = m0 + r, l = m & (L_-1);
        int lp = l < 3 ? l : 3;
        float sum = 0.f;
        int kmin = (l >= 3) ? 0 : (3 - l);
        #pragma unroll
        for (int k = 0; k < 4; k++)
            if (k >= kmin) sum += g_H4[(size_t)(m-3+k)*H4N + k*128 + j];
        sG[r*130 + j] = g_const[lp*NOUT + j] + sum*INV_ESCALE;
    }
    __syncthreads();
    #pragma unroll
    for (int it = 0; it < 16; it++){
        int p = tid + it*256;
        int s = p >> 6;
        int r = p & 63;
        float xs = sG[r*130 + s];
        float dv = sG[r*130 + 64 + s];
        float dt = dv > 20.f ? dv : log1pf(expf(dv));
        float Aa = -expf(A_log[s]);
        float dA = expf(Aa*dt);
        float dBx = (1.f - dA)/Aa * xs;
        int m = m0 + r;
        int b = m >> 11;
        int l = m & (L_-1);
        size_t o = ((size_t)(b*DSTATE + s))*L_ + l;
        g_dA[o]  = dA;
        g_dBx[o] = dBx;
    }
}

// ======================= scan (coalesced zT output) ========================
__global__ __launch_bounds__(256)
void scan_kernel(){
    const int bs = blockIdx.x;
    const int t  = threadIdx.x;
    const size_t base = (size_t)bs * L_;
    float a[8], bb[8];
    #pragma unroll
    for (int i=0;i<8;i++){ a[i] = g_dA[base + t*8 + i]; bb[i] = g_dBx[base + t*8 + i]; }

    float Ai = 1.f, Bi = 0.f;
    #pragma unroll
    for (int i=0;i<8;i++){ Bi = Bi*a[i] + bb[i]; Ai *= a[i]; }

    const unsigned lane = t & 31, wid = t >> 5;
    #pragma unroll
    for (int off = 1; off < 32; off <<= 1){
        float Au = __shfl_up_sync(0xffffffffu, Ai, off);
        float Bu = __shfl_up_sync(0xffffffffu, Bi, off);
        if (lane >= off){ Bi = Ai*Bu + Bi; Ai = Ai*Au; }
    }
    __shared__ float wA[8], wB[8], pB[8];
    if (lane == 31){ wA[wid] = Ai; wB[wid] = Bi; }
    __syncthreads();
    if (t == 0){
        float cB = 0.f;
        #pragma unroll
        for (int w = 0; w < 8; w++){
            pB[w] = cB;
            cB = cB*wA[w] + wB[w];
        }
    }
    __syncthreads();
    float eA = __shfl_up_sync(0xffffffffu, Ai, 1);
    float eB = __shfl_up_sync(0xffffffffu, Bi, 1);
    if (lane == 0){ eA = 1.f; eB = 0.f; }
    float z = eA*pB[wid] + eB;

    __nv_bfloat16 hb[8], lb[8];
    #pragma unroll
    for (int i = 0; i < 8; i++){
        z = a[i]*z + bb[i];
        bf_split(z, hb[i], lb[i]);
    }
    *(uint4*)&g_zThi[base + t*8] = *(uint4*)hb;
    *(uint4*)&g_zTlo[base + t*8] = *(uint4*)lb;
}

// zT [b*64+s][l] -> z [m][s]
__global__ __launch_bounds__(256)
void transpose_z(){
    __shared__ __nv_bfloat16 th[64][66];
    __shared__ __nv_bfloat16 tl[64][66];
    const int tid = threadIdx.x;
    const int l0  = blockIdx.x * 64;
    const int b   = blockIdx.y;
    #pragma unroll
    for (int it = 0; it < 16; it++){
        int i = tid + it*256;
        int s = i >> 6, lo = i & 63;
        size_t o = (size_t)(b*DSTATE + s)*L_ + l0 + lo;
        th[s][lo] = g_zThi[o];
        tl[s][lo] = g_zTlo[o];
    }
    __syncthreads();
    #pragma unroll
    for (int it = 0; it < 16; it++){
        int i = tid + it*256;
        int l = i >> 6, s = i & 63;
        size_t o = (size_t)(b*L_ + l0 + l)*DSTATE + s;
        g_zhi[o] = th[s][l];
        g_zlo[o] = tl[s][l];
    }
}

// ======================= launch ============================================
extern "C" void kernel_launch(void* const* d_in, const int* in_sizes, int n_in,
                              void* d_out, int out_size){
    const float* x      = (const float*)d_in[0];
    const float* W_in   = (const float*)d_in[1];
    const float* b_in   = (const float*)d_in[2];
    const float* conv_w = (const float*)d_in[3];
    const float* conv_b = (const float*)d_in[4];
    const float* W_x    = (const float*)d_in[5];
    const float* b_x    = (const float*)d_in[6];
    const float* W_dt   = (const float*)d_in[7];
    const float* b_dt   = (const float*)d_in[8];
    const float* A_log  = (const float*)d_in[9];
    const float* D_mat  = (const float*)d_in[10];
    const float* W_out  = (const float*)d_in[11];
    const float* b_out  = (const float*)d_in[12];
    float* out = (float*)d_out;

    cudaFuncSetAttribute(mma_gemm<0>, cudaFuncAttributeMaxDynamicSharedMemorySize, MG_SMEM);
    cudaFuncSetAttribute(mma_gemm<2>, cudaFuncAttributeMaxDynamicSharedMemorySize, MG_SMEM);
    cudaFuncSetAttribute(mma_h4f,     cudaFuncAttributeMaxDynamicSharedMemorySize, MH_SMEM);

    float *pEp;
    cudaGetSymbolAddress((void**)&pEp, g_Ep);
    __nv_bfloat16 *pAbh, *pAbl, *pWTh, *pWTl, *pZh, *pZl, *pCth, *pCtl;
    cudaGetSymbolAddress((void**)&pAbh, g_Abhi);
    cudaGetSymbolAddress((void**)&pAbl, g_Ablo);
    cudaGetSymbolAddress((void**)&pWTh, g_WThi);
    cudaGetSymbolAddress((void**)&pWTl, g_WTlo);
    cudaGetSymbolAddress((void**)&pZh,  g_zhi);
    cudaGetSymbolAddress((void**)&pZl,  g_zlo);
    cudaGetSymbolAddress((void**)&pCth, g_Cthi);
    cudaGetSymbolAddress((void**)&pCtl, g_Ctlo);

    // 1. all independent prep + ct GEMM in one wave
    prep_all<<<PREP_BLOCKS, 256>>>(x, W_in, conv_w, conv_b,
                                   W_x, b_x, W_dt, b_dt, b_in, W_out, D_mat);

    // 2. E = Abig @ Win (3-pass bf16, split-K=4)
    mma_gemm<2><<<dim3(H4N/128, DMODEL/128, ESPLIT), 256, MG_SMEM>>>(
        pAbh, pAbl, pWTh, pWTl, pEp, nullptr,
        DINNER, DINNER, DINNER/ESPLIT, DMODEL, (size_t)H4N*DMODEL, 1.0f);

    // 3. reduce_E (fp16, x4096) + reduce_ct (bf16)
    reduce_all<<<2048 + 256, 256>>>();

    // 4. H4 = fp16(X) @ E'^T (2-pass fp16)
    mma_h4f<<<dim3(MTOT/128, H4N/128), 256, MH_SMEM>>>();

    // 5-7. combine (descale), scan, transpose
    combine<<<MTOT/64, 256>>>(A_log);
    scan_kernel<<<B_*DSTATE, 256>>>();
    transpose_z<<<dim3(L_/64, B_), 256>>>();

    // 8. out = z @ Ct^T + b_out (3-pass bf16)
    mma_gemm<0><<<dim3(MTOT/128, DMODEL/128, 1), 256, MG_SMEM>>>(
        pZh, pZl, pCth, pCtl, out, b_out,
        DSTATE, DSTATE, DSTATE, DMODEL, 0, 1.0f);
}

// round 14
// speedup vs baseline: 1.3598x; 1.0910x over previous
#include <cuda_runtime.h>
#include <cuda_bf16.h>
#include <cuda_fp16.h>
#include <math.h>
#include <stdint.h>

#define B_      4
#define L_      2048
#define DMODEL  1024
#define DINNER  2048
#define DSTATE  64
#define KCONV   4
#define MTOT    (B_*L_)     // 8192
#define NOUT    128         // 2*DSTATE (x_ssm | dt)
#define CTSPLIT 16
#define ESPLIT  4
#define H4N     512         // 4*NOUT rows of Eall
#define INV_ESCALE  2.44140625e-4f     // 1/4096 (H4 carries x_ssm*4096)

// ---------------- scratch (device globals: no allocation allowed) ----------
__device__ float g_const[4*NOUT];
__device__ float g_Ctp[CTSPLIT*DMODEL*DSTATE];
__device__ __align__(16) __half g_Cthf[DMODEL*DSTATE];        // Ct*1024 hi
__device__ __align__(16) __half g_Ctlf[DMODEL*DSTATE];        // Ct*1024 lo
__device__ float g_Ep[ESPLIT*H4N*DMODEL];                     // partials (x 2^20)
__device__ __align__(16) __half g_Ehf[H4N*DMODEL];            // E*4096 hi
__device__ __align__(16) __half g_Elf[H4N*DMODEL];            // E*4096 lo
__device__ __align__(16) __half g_Abf[H4N*DINNER];            // Abig*1024 fp16
__device__ __align__(16) __half g_WTh[DMODEL*DINNER];         // Win^T*1024 hi
__device__ __align__(16) __half g_WTl[DMODEL*DINNER];         // Win^T*1024 lo
__device__ __align__(16) __half g_Xh[(size_t)MTOT*DMODEL];    // fp16(x)
__device__ __align__(16) __half g_zTf[B_*DSTATE*L_];          // z [b*64+s][l] fp16
__device__ __align__(16) __half g_zf[MTOT*DSTATE];            // z [m][s] fp16
__device__ __align__(16) float g_H4[(size_t)MTOT*H4N];
__device__ float g_dA[B_*DSTATE*L_];
__device__ float g_dBx[B_*DSTATE*L_];

// ======================= helpers ===========================================
__device__ __forceinline__ uint32_t smem_u32(const void* p){
    uint32_t a;
    asm("{ .reg .u64 t; cvta.to.shared.u64 t, %1; cvt.u32.u64 %0, t; }" : "=r"(a) : "l"(p));
    return a;
}
__device__ __forceinline__ void cp16(uint32_t saddr, const void* g){
    asm volatile("cp.async.ca.shared.global [%0], [%1], 16;" :: "r"(saddr), "l"(g));
}
__device__ __forceinline__ void cp_commit(){ asm volatile("cp.async.commit_group;"); }
__device__ __forceinline__ void cp_wait0(){ asm volatile("cp.async.wait_group 0;"); }

__device__ __forceinline__ void ldsm4(uint32_t* r, uint32_t addr){
    asm volatile("ldmatrix.sync.aligned.m8n8.x4.shared.b16 {%0,%1,%2,%3}, [%4];"
        : "=r"(r[0]), "=r"(r[1]), "=r"(r[2]), "=r"(r[3]) : "r"(addr));
}
__device__ __forceinline__ void mma16816h(float* d, const uint32_t* a, uint32_t b0, uint32_t b1){
    asm volatile("mma.sync.aligned.m16n8k16.row.col.f32.f16.f16.f32 "
        "{%0,%1,%2,%3}, {%4,%5,%6,%7}, {%8,%9}, {%0,%1,%2,%3};"
        : "+f"(d[0]), "+f"(d[1]), "+f"(d[2]), "+f"(d[3])
        : "r"(a[0]), "r"(a[1]), "r"(a[2]), "r"(a[3]), "r"(b0), "r"(b1));
}
__device__ __forceinline__ void hf_split(float v, __half& h, __half& l){
    h = __float2half(v);
    l = __float2half(v - __half2float(h));
}

// ======================= fused prep mega-kernel ============================
// Roles: [0,4096) absplit(fp16 x1024) | [4096,6144) wT(fp16 hi/lo x1024)
//        [6144,10240) xsplit(fp16) | [10240,10752) const | [10752,11008) ct_split
#define PREP_BLOCKS (4096 + 2048 + 4096 + 512 + 256)

__global__ __launch_bounds__(256)
void prep_all(const float* __restrict__ x,    const float* __restrict__ Win,
              const float* __restrict__ convw, const float* __restrict__ convb,
              const float* __restrict__ Wx,   const float* __restrict__ b_x,
              const float* __restrict__ Wdt,  const float* __restrict__ b_dt,
              const float* __restrict__ b_in,
              const float* __restrict__ Wout, const float* __restrict__ Dmat){
    __shared__ __align__(16) char sh[8448];
    const int blk = blockIdx.x;
    const int tid = threadIdx.x;

    if (blk < 4096){
        // ---- absplit: Abig*1024 -> fp16 single
        int idx = blk*256 + tid;
        int c   = idx & (DINNER-1);
        int row = idx >> 11;
        int k4  = row >> 7, j = row & 127;
        float p = (j < DSTATE) ? Wx[j*DINNER + c] : Wdt[(j-DSTATE)*DINNER + c];
        float v = p * convw[c*KCONV + k4] * 1024.0f;
        g_Abf[idx] = __float2half(v);
    } else if (blk < 6144){
        // ---- wT: Win [c][dm] -> [dm][c] fp16 hi/lo x1024
        float (*t)[33] = (float(*)[33])sh;
        int b  = blk - 4096;
        int n0 = (b & 31)*32;
        int k0 = (b >> 5)*32;
        int tx = tid & 31, ty = tid >> 5;
        #pragma unroll
        for (int p = 0; p < 4; p++){
            int k = ty + p*8;
            t[k][tx] = Win[(size_t)(k0+k)*DMODEL + n0 + tx];
        }
        __syncthreads();
        #pragma unroll
        for (int p = 0; p < 4; p++){
            int n = ty + p*8;
            float v = t[tx][n] * 1024.0f;
            __half h, l; hf_split(v, h, l);
            size_t o = (size_t)(n0+n)*DINNER + k0 + tx;
            g_WTh[o] = h; g_WTl[o] = l;
        }
    } else if (blk < 10240){
        // ---- xsplit: fp16 single (8 floats per thread)
        size_t i = ((size_t)(blk - 6144)*256 + tid)*8;
        float4 v0 = *(const float4*)&x[i];
        float4 v1 = *(const float4*)&x[i+4];
        __half h[8];
        h[0]=__float2half(v0.x); h[1]=__float2half(v0.y);
        h[2]=__float2half(v0.z); h[3]=__float2half(v0.w);
        h[4]=__float2half(v1.x); h[5]=__float2half(v1.y);
        h[6]=__float2half(v1.z); h[7]=__float2half(v1.w);
        *(uint4*)&g_Xh[i] = *(uint4*)h;
    } else if (blk < 10752){
        // ---- const
        float* red = (float*)sh;
        int b  = blk - 10240;
        int j  = b & 127;
        int lp = b >> 7;
        int kstart = 3 - lp;
        float partial = 0.f;
        for (int c = tid; c < DINNER; c += 256){
            float sw = 0.f;
            #pragma unroll
            for (int k = 0; k < 4; k++) if (k >= kstart) sw += convw[c*4 + k];
            float p = (j < DSTATE) ? Wx[j*DINNER + c] : Wdt[(j-DSTATE)*DINNER + c];
            partial += p * (convb[c] + b_in[c]*sw);
        }
        red[tid] = partial; __syncthreads();
        for (int s = 128; s > 0; s >>= 1){ if (tid < s) red[tid] += red[tid+s]; __syncthreads(); }
        if (tid == 0){
            float bias = (j < DSTATE) ? b_x[j] : b_dt[j-DSTATE];
            g_const[lp*NOUT + j] = red[0] + bias;
        }
    } else {
        // ---- ct_split
        float (*As)[65] = (float(*)[65])sh;
        float (*Bs)[65] = (float(*)[65])(sh + 4224);
        int b  = blk - 10752;
        int m0 = (b & 15)*64;
        int z  = b >> 4;
        int kbase = z * (DINNER/CTSPLIT);
        int tx = tid & 15, ty = tid >> 4;
        float acc[4][4];
        #pragma unroll
        for (int a=0;a<4;a++)
            #pragma unroll
            for (int c=0;c<4;c++) acc[a][c] = 0.f;

        for (int kk = 0; kk < DINNER/CTSPLIT; kk += 16){
            #pragma unroll
            for (int idx = tid; idx < 64*16; idx += 256){
                int m = idx >> 4, kq = idx & 15;
                As[kq][m] = Wout[(size_t)(m0+m)*DINNER + kbase + kk + kq];
            }
            #pragma unroll
            for (int idx = tid; idx < 64*16; idx += 256){
                int n = idx >> 4, kq = idx & 15;
                Bs[kq][n] = Dmat[(size_t)n*DINNER + kbase + kk + kq];
            }
            __syncthreads();
            #pragma unroll
            for (int i = 0; i < 16; i++){
                float af[4], bf[4];
                #pragma unroll
                for (int t2=0;t2<4;t2++) af[t2] = As[i][ty*4+t2];
                #pragma unroll
                for (int t2=0;t2<4;t2++) bf[t2] = Bs[i][tx*4+t2];
                #pragma unroll
                for (int a=0;a<4;a++)
                    #pragma unroll
                    for (int c=0;c<4;c++) acc[a][c] += af[a]*bf[c];
            }
            __syncthreads();
        }
        float* outp = g_Ctp + (size_t)z*DMODEL*DSTATE;
        #pragma unroll
        for (int a=0;a<4;a++)
            #pragma unroll
            for (int c=0;c<4;c++)
                outp[(size_t)(m0+ty*4+a)*DSTATE + tx*4 + c] = acc[a][c];
    }
}

// ======================= fused reduce kernel ===============================
// [0,2048): reduce_E (partials x2^20 -> E*4096 fp16 hi/lo = /256)
// [2048,2304): reduce_ct (-> Ct*1024 fp16 hi/lo)
__global__ __launch_bounds__(256)
void reduce_all(){
    const int blk = blockIdx.x;
    const int tid = threadIdx.x;
    if (blk < 2048){
        int i = blk*256 + tid;
        float s = 0.f;
        #pragma unroll
        for (int z = 0; z < ESPLIT; z++) s += g_Ep[(size_t)z*H4N*DMODEL + i];
        float ss = s * (1.0f/256.0f);
        __half h, l; hf_split(ss, h, l);
        g_Ehf[i] = h; g_Elf[i] = l;
    } else {
        int i = (blk - 2048)*256 + tid;
        float s = 0.f;
        #pragma unroll
        for (int z = 0; z < CTSPLIT; z++) s += g_Ctp[(size_t)z*DMODEL*DSTATE + i];
        float ss = s * 1024.0f;
        __half h, l; hf_split(ss, h, l);
        g_Cthf[i] = h; g_Ctlf[i] = l;
    }
}

// ======================= unified 2-pass fp16 mma GEMM ======================
// C = A @ (Bh+Bl)^T. A single fp16, B fp16 hi/lo, fp32 accum, 2 MMA groups.
// BM=BN=128, BK=32, 8 warps (64x32). 3 tiles/stage, 2 stages = 60KB smem.
// MODE 0: C += bias (if set), scaled by outScale. MODE 2: split-K partial.
#define MG_PITCH 80
#define MG_TILE  (128*MG_PITCH)       // 10240 B
#define MH_STG   (3*MG_TILE)          // 30720 B
#define MH_SMEM  (2*MH_STG)           // 61440 B

__device__ __forceinline__ void mh_issue3(uint32_t base,
        const __half* __restrict__ A, const __half* __restrict__ Bh,
        const __half* __restrict__ Bl,
        int m0, int n0, int lda, int ldb, int kk, int tid){
    #pragma unroll
    for (int i = tid; i < 512; i += 256){
        int r = i >> 2, c = i & 3;
        uint32_t o = r*MG_PITCH + c*16;
        size_t ga = (size_t)(m0 + r)*lda + kk + c*8;
        size_t gb = (size_t)(n0 + r)*ldb + kk + c*8;
        cp16(base +             o, A  + ga);
        cp16(base + MG_TILE   + o, Bh + gb);
        cp16(base + 2*MG_TILE + o, Bl + gb);
    }
    cp_commit();
}

template<int MODE>
__global__ __launch_bounds__(256, 2)
void mma_fp16(const __half* __restrict__ A, const __half* __restrict__ Bh,
              const __half* __restrict__ Bl,
              float* __restrict__ C, const float* __restrict__ bias,
              int lda, int ldb, int kLen, int ldc, size_t sliceStride, float outScale){
    extern __shared__ __align__(16) char dsm[];
    const int tid  = threadIdx.x;
    const int wid  = tid >> 5, lane = tid & 31;
    const int m0   = blockIdx.x * 128;
    const int n0   = blockIdx.y * 128;
    const int kbase= blockIdx.z * kLen;
    const int wm   = (wid >> 2) * 64;
    const int wn   = (wid & 3) * 32;
    const uint32_t sbu = smem_u32(dsm);
    const int NIT = kLen >> 5;

    float acc[4][4][4];
    #pragma unroll
    for (int a=0;a<4;a++)
        #pragma unroll
        for (int b=0;b<4;b++)
            #pragma unroll
            for (int c=0;c<4;c++) acc[a][b][c] = 0.f;

    mh_issue3(sbu, A, Bh, Bl, m0, n0, lda, ldb, kbase, tid);
    cp_wait0();
    __syncthreads();

    for (int t = 0; t < NIT; t++){
        int buf = t & 1;
        if (t + 1 < NIT)
            mh_issue3(sbu + (buf^1)*MH_STG, A, Bh, Bl,
                      m0, n0, lda, ldb, kbase + (t+1)*32, tid);

        const uint32_t sb = sbu + buf*MH_STG;
        #pragma unroll
        for (int ks = 0; ks < 2; ks++){
            uint32_t ah[4][4], bh[2][4], bl[2][4];
            #pragma unroll
            for (int mb = 0; mb < 4; mb++){
                int row = wm + mb*16 + (lane & 15);
                uint32_t o = row*MG_PITCH + ks*32 + (lane >> 4)*16;
                ldsm4(ah[mb], sb + o);
            }
            #pragma unroll
            for (int nb2 = 0; nb2 < 2; nb2++){
                int row = wn + nb2*16 + ((lane >> 3) & 1)*8 + (lane & 7);
                uint32_t o = row*MG_PITCH + ks*32 + (lane >> 4)*16;
                ldsm4(bh[nb2], sb + MG_TILE + o);
                ldsm4(bl[nb2], sb + 2*MG_TILE + o);
            }
            #pragma unroll
            for (int mb = 0; mb < 4; mb++)
                #pragma unroll
                for (int nb = 0; nb < 4; nb++){
                    int nb2 = nb >> 1, odd = nb & 1;
                    mma16816h(acc[mb][nb], ah[mb], bh[nb2][odd?1:0], bh[nb2][odd?3:2]);
                }
            #pragma unroll
            for (int mb = 0; mb < 4; mb++)
                #pragma unroll
                for (int nb = 0; nb < 4; nb++){
                    int nb2 = nb >> 1, odd = nb & 1;
                    mma16816h(acc[mb][nb], ah[mb], bl[nb2][odd?1:0], bl[nb2][odd?3:2]);
                }
        }

        if (t + 1 < NIT){ cp_wait0(); __syncthreads(); }
    }

    float* Co = (MODE == 2) ? (C + (size_t)blockIdx.z*sliceStride) : C;
    #pragma unroll
    for (int mb = 0; mb < 4; mb++){
        #pragma unroll
        for (int nb = 0; nb < 4; nb++){
            int r = m0 + wm + mb*16 + (lane >> 2);
            int c = n0 + wn + nb*8 + (lane & 3)*2;
            float2 v0 = make_float2(acc[mb][nb][0]*outScale, acc[mb][nb][1]*outScale);
            float2 v1 = make_float2(acc[mb][nb][2]*outScale, acc[mb][nb][3]*outScale);
            if (MODE == 0 && bias){
                float b0 = bias[c], b1 = bias[c+1];
                v0.x += b0; v0.y += b1;
                v1.x += b0; v1.y += b1;
            }
            *(float2*)&Co[(size_t)r*ldc + c]       = v0;
            *(float2*)&Co[(size_t)(r+8)*ldc + c]   = v1;
        }
    }
}

// ======================= combine (descale + shift-sum + SSM param) =========
__global__ __launch_bounds__(256)
void combine(const float* __restrict__ A_log){
    const int tid = threadIdx.x;
    const int m0  = blockIdx.x * 64;
    __shared__ float sG[64*130];
    #pragma unroll
    for (int it = 0; it < 32; it++){
        int i = tid + it*256;
        int r = i >> 7, j = i & 127;
        int m = m0 + r, l = m & (L_-1);
        int lp = l < 3 ? l : 3;
        float sum = 0.f;
        int kmin = (l >= 3) ? 0 : (3 - l);
        #pragma unroll
        for (int k = 0; k < 4; k++)
            if (k >= kmin) sum += g_H4[(size_t)(m-3+k)*H4N + k*128 + j];
        sG[r*130 + j] = g_const[lp*NOUT + j] + sum*INV_ESCALE;
    }
    __syncthreads();
    #pragma unroll
    for (int it = 0; it < 16; it++){
        int p = tid + it*256;
        int s = p >> 6;
        int r = p & 63;
        float xs = sG[r*130 + s];
        float dv = sG[r*130 + 64 + s];
        float dt = dv > 20.f ? dv : log1pf(expf(dv));
        float Aa = -expf(A_log[s]);
        float dA = expf(Aa*dt);
        float dBx = (1.f - dA)/Aa * xs;
        int m = m0 + r;
        int b = m >> 11;
        int l = m & (L_-1);
        size_t o = ((size_t)(b*DSTATE + s))*L_ + l;
        g_dA[o]  = dA;
        g_dBx[o] = dBx;
    }
}

// ======================= scan (fp16 zT output) =============================
__global__ __launch_bounds__(256)
void scan_kernel(){
    const int bs = blockIdx.x;
    const int t  = threadIdx.x;
    const size_t base = (size_t)bs * L_;
    float a[8], bb[8];
    #pragma unroll
    for (int i=0;i<8;i++){ a[i] = g_dA[base + t*8 + i]; bb[i] = g_dBx[base + t*8 + i]; }

    float Ai = 1.f, Bi = 0.f;
    #pragma unroll
    for (int i=0;i<8;i++){ Bi = Bi*a[i] + bb[i]; Ai *= a[i]; }

    const unsigned lane = t & 31, wid = t >> 5;
    #pragma unroll
    for (int off = 1; off < 32; off <<= 1){
        float Au = __shfl_up_sync(0xffffffffu, Ai, off);
        float Bu = __shfl_up_sync(0xffffffffu, Bi, off);
        if (lane >= off){ Bi = Ai*Bu + Bi; Ai = Ai*Au; }
    }
    __shared__ float wA[8], wB[8], pB[8];
    if (lane == 31){ wA[wid] = Ai; wB[wid] = Bi; }
    __syncthreads();
    if (t == 0){
        float cB = 0.f;
        #pragma unroll
        for (int w = 0; w < 8; w++){
            pB[w] = cB;
            cB = cB*wA[w] + wB[w];
        }
    }
    __syncthreads();
    float eA = __shfl_up_sync(0xffffffffu, Ai, 1);
    float eB = __shfl_up_sync(0xffffffffu, Bi, 1);
    if (lane == 0){ eA = 1.f; eB = 0.f; }
    float z = eA*pB[wid] + eB;

    __half hb[8];
    #pragma unroll
    for (int i = 0; i < 8; i++){
        z = a[i]*z + bb[i];
        hb[i] = __float2half(z);
    }
    *(uint4*)&g_zTf[base + t*8] = *(uint4*)hb;
}

// zT [b*64+s][l] -> z [m][s] fp16
__global__ __launch_bounds__(256)
void transpose_z(){
    __shared__ __half th[64][66];
    const int tid = threadIdx.x;
    const int l0  = blockIdx.x * 64;
    const int b   = blockIdx.y;
    #pragma unroll
    for (int it = 0; it < 16; it++){
        int i = tid + it*256;
        int s = i >> 6, lo = i & 63;
        th[s][lo] = g_zTf[(size_t)(b*DSTATE + s)*L_ + l0 + lo];
    }
    __syncthreads();
    #pragma unroll
    for (int it = 0; it < 16; it++){
        int i = tid + it*256;
        int l = i >> 6, s = i & 63;
        g_zf[(size_t)(b*L_ + l0 + l)*DSTATE + s] = th[s][l];
    }
}

// ======================= launch ============================================
extern "C" void kernel_launch(void* const* d_in, const int* in_sizes, int n_in,
                              void* d_out, int out_size){
    const float* x      = (const float*)d_in[0];
    const float* W_in   = (const float*)d_in[1];
    const float* b_in   = (const float*)d_in[2];
    const float* conv_w = (const float*)d_in[3];
    const float* conv_b = (const float*)d_in[4];
    const float* W_x    = (const float*)d_in[5];
    const float* b_x    = (const float*)d_in[6];
    const float* W_dt   = (const float*)d_in[7];
    const float* b_dt   = (const float*)d_in[8];
    const float* A_log  = (const float*)d_in[9];
    const float* D_mat  = (const float*)d_in[10];
    const float* W_out  = (const float*)d_in[11];
    const float* b_out  = (const float*)d_in[12];
    float* out = (float*)d_out;

    cudaFuncSetAttribute(mma_fp16<0>, cudaFuncAttributeMaxDynamicSharedMemorySize, MH_SMEM);
    cudaFuncSetAttribute(mma_fp16<2>, cudaFuncAttributeMaxDynamicSharedMemorySize, MH_SMEM);

    float *pEp, *pH4;
    cudaGetSymbolAddress((void**)&pEp, g_Ep);
    cudaGetSymbolAddress((void**)&pH4, g_H4);
    __half *pAbf, *pWTh, *pWTl, *pEh, *pEl, *pXh, *pZf, *pCth, *pCtl;
    cudaGetSymbolAddress((void**)&pAbf, g_Abf);
    cudaGetSymbolAddress((void**)&pWTh, g_WTh);
    cudaGetSymbolAddress((void**)&pWTl, g_WTl);
    cudaGetSymbolAddress((void**)&pEh,  g_Ehf);
    cudaGetSymbolAddress((void**)&pEl,  g_Elf);
    cudaGetSymbolAddress((void**)&pXh,  g_Xh);
    cudaGetSymbolAddress((void**)&pZf,  g_zf);
    cudaGetSymbolAddress((void**)&pCth, g_Cthf);
    cudaGetSymbolAddress((void**)&pCtl, g_Ctlf);

    // 1. all independent prep + ct GEMM in one wave
    prep_all<<<PREP_BLOCKS, 256>>>(x, W_in, conv_w, conv_b,
                                   W_x, b_x, W_dt, b_dt, b_in, W_out, D_mat);

    // 2. E partials = (Abig*1024) @ (Win^T*1024)^T  (2-pass fp16, split-K=4)
    mma_fp16<2><<<dim3(H4N/128, DMODEL/128, ESPLIT), 256, MH_SMEM>>>(
        pAbf, pWTh, pWTl, pEp, nullptr,
        DINNER, DINNER, DINNER/ESPLIT, DMODEL, (size_t)H4N*DMODEL, 1.0f);

    // 3. reduce_E (/256 -> E*4096 hi/lo) + reduce_ct (*1024 hi/lo)
    reduce_all<<<2048 + 256, 256>>>();

    // 4. H4 = fp16(X) @ (E*4096)^T
    mma_fp16<0><<<dim3(MTOT/128, H4N/128, 1), 256, MH_SMEM>>>(
        pXh, pEh, pEl, pH4, nullptr,
        DMODEL, DMODEL, DMODEL, H4N, 0, 1.0f);

    // 5-7. combine (descale), scan (fp16 z), transpose
    combine<<<MTOT/64, 256>>>(A_log);
    scan_kernel<<<B_*DSTATE, 256>>>();
    transpose_z<<<dim3(L_/64, B_), 256>>>();

    // 8. out = z @ (Ct*1024)^T / 1024 + b_out
    mma_fp16<0><<<dim3(MTOT/128, DMODEL/128, 1), 256, MH_SMEM>>>(
        pZf, pCth, pCtl, out, b_out,
        DSTATE, DSTATE, DSTATE, DMODEL, 0, 9.765625e-4f);
}

// round 15
// speedup vs baseline: 1.5937x; 1.1720x over previous
#include <cuda_runtime.h>
#include <cuda_bf16.h>
#include <cuda_fp16.h>
#include <math.h>
#include <stdint.h>

#define B_      4
#define L_      2048
#define DMODEL  1024
#define DINNER  2048
#define DSTATE  64
#define KCONV   4
#define MTOT    (B_*L_)     // 8192
#define NOUT    128         // 2*DSTATE (x_ssm | dt)
#define CTSPLIT 16
#define ESPLIT  4
#define H4N     512         // 4*NOUT rows of Eall
#define INV_ESCALE  2.44140625e-4f     // 1/4096 (H4 carries x_ssm*4096)

// ---------------- scratch (device globals: no allocation allowed) ----------
__device__ float g_const[4*NOUT];
__device__ float g_Ctp[CTSPLIT*DMODEL*DSTATE];
__device__ __align__(16) __half g_Cthf[DMODEL*DSTATE];        // Ct*1024 hi
__device__ __align__(16) __half g_Ctlf[DMODEL*DSTATE];        // Ct*1024 lo
__device__ float g_Ep[ESPLIT*H4N*DMODEL];                     // partials (x 2^20)
__device__ __align__(16) __half g_Ehf[H4N*DMODEL];            // E*4096 fp16
__device__ __align__(16) __half g_Abf[H4N*DINNER];            // Abig*1024 fp16
__device__ __align__(16) __half g_WTh[DMODEL*DINNER];         // Win^T*1024 hi
__device__ __align__(16) __half g_WTl[DMODEL*DINNER];         // Win^T*1024 lo
__device__ __align__(16) __half g_Xh[(size_t)MTOT*DMODEL];    // fp16(x)
__device__ __align__(16) __half g_zTf[B_*DSTATE*L_];          // z [b*64+s][l] fp16
__device__ __align__(16) __half g_zf[MTOT*DSTATE];            // z [m][s] fp16
__device__ __align__(16) float g_H4[(size_t)MTOT*H4N];
__device__ float g_dA[B_*DSTATE*L_];
__device__ float g_dBx[B_*DSTATE*L_];

// ======================= helpers ===========================================
__device__ __forceinline__ uint32_t smem_u32(const void* p){
    uint32_t a;
    asm("{ .reg .u64 t; cvta.to.shared.u64 t, %1; cvt.u32.u64 %0, t; }" : "=r"(a) : "l"(p));
    return a;
}
__device__ __forceinline__ void cp16(uint32_t saddr, const void* g){
    asm volatile("cp.async.ca.shared.global [%0], [%1], 16;" :: "r"(saddr), "l"(g));
}
__device__ __forceinline__ void cp_commit(){ asm volatile("cp.async.commit_group;"); }
__device__ __forceinline__ void cp_wait0(){ asm volatile("cp.async.wait_group 0;"); }

__device__ __forceinline__ void ldsm4(uint32_t* r, uint32_t addr){
    asm volatile("ldmatrix.sync.aligned.m8n8.x4.shared.b16 {%0,%1,%2,%3}, [%4];"
        : "=r"(r[0]), "=r"(r[1]), "=r"(r[2]), "=r"(r[3]) : "r"(addr));
}
__device__ __forceinline__ void mma16816h(float* d, const uint32_t* a, uint32_t b0, uint32_t b1){
    asm volatile("mma.sync.aligned.m16n8k16.row.col.f32.f16.f16.f32 "
        "{%0,%1,%2,%3}, {%4,%5,%6,%7}, {%8,%9}, {%0,%1,%2,%3};"
        : "+f"(d[0]), "+f"(d[1]), "+f"(d[2]), "+f"(d[3])
        : "r"(a[0]), "r"(a[1]), "r"(a[2]), "r"(a[3]), "r"(b0), "r"(b1));
}
__device__ __forceinline__ void hf_split(float v, __half& h, __half& l){
    h = __float2half(v);
    l = __float2half(v - __half2float(h));
}

// ======================= fused prep mega-kernel ============================
// Roles: [0,4096) absplit(fp16 x1024) | [4096,6144) wT(fp16 hi/lo x1024)
//        [6144,10240) xsplit(fp16) | [10240,10752) const | [10752,11008) ct_split
#define PREP_BLOCKS (4096 + 2048 + 4096 + 512 + 256)

__global__ __launch_bounds__(256)
void prep_all(const float* __restrict__ x,    const float* __restrict__ Win,
              const float* __restrict__ convw, const float* __restrict__ convb,
              const float* __restrict__ Wx,   const float* __restrict__ b_x,
              const float* __restrict__ Wdt,  const float* __restrict__ b_dt,
              const float* __restrict__ b_in,
              const float* __restrict__ Wout, const float* __restrict__ Dmat){
    __shared__ __align__(16) char sh[8448];
    const int blk = blockIdx.x;
    const int tid = threadIdx.x;

    if (blk < 4096){
        // ---- absplit: Abig*1024 -> fp16 single
        int idx = blk*256 + tid;
        int c   = idx & (DINNER-1);
        int row = idx >> 11;
        int k4  = row >> 7, j = row & 127;
        float p = (j < DSTATE) ? Wx[j*DINNER + c] : Wdt[(j-DSTATE)*DINNER + c];
        float v = p * convw[c*KCONV + k4] * 1024.0f;
        g_Abf[idx] = __float2half(v);
    } else if (blk < 6144){
        // ---- wT: Win [c][dm] -> [dm][c] fp16 hi/lo x1024
        float (*t)[33] = (float(*)[33])sh;
        int b  = blk - 4096;
        int n0 = (b & 31)*32;
        int k0 = (b >> 5)*32;
        int tx = tid & 31, ty = tid >> 5;
        #pragma unroll
        for (int p = 0; p < 4; p++){
            int k = ty + p*8;
            t[k][tx] = Win[(size_t)(k0+k)*DMODEL + n0 + tx];
        }
        __syncthreads();
        #pragma unroll
        for (int p = 0; p < 4; p++){
            int n = ty + p*8;
            float v = t[tx][n] * 1024.0f;
            __half h, l; hf_split(v, h, l);
            size_t o = (size_t)(n0+n)*DINNER + k0 + tx;
            g_WTh[o] = h; g_WTl[o] = l;
        }
    } else if (blk < 10240){
        // ---- xsplit: fp16 single (8 floats per thread)
        size_t i = ((size_t)(blk - 6144)*256 + tid)*8;
        float4 v0 = *(const float4*)&x[i];
        float4 v1 = *(const float4*)&x[i+4];
        __half h[8];
        h[0]=__float2half(v0.x); h[1]=__float2half(v0.y);
        h[2]=__float2half(v0.z); h[3]=__float2half(v0.w);
        h[4]=__float2half(v1.x); h[5]=__float2half(v1.y);
        h[6]=__float2half(v1.z); h[7]=__float2half(v1.w);
        *(uint4*)&g_Xh[i] = *(uint4*)h;
    } else if (blk < 10752){
        // ---- const
        float* red = (float*)sh;
        int b  = blk - 10240;
        int j  = b & 127;
        int lp = b >> 7;
        int kstart = 3 - lp;
        float partial = 0.f;
        for (int c = tid; c < DINNER; c += 256){
            float sw = 0.f;
            #pragma unroll
            for (int k = 0; k < 4; k++) if (k >= kstart) sw += convw[c*4 + k];
            float p = (j < DSTATE) ? Wx[j*DINNER + c] : Wdt[(j-DSTATE)*DINNER + c];
            partial += p * (convb[c] + b_in[c]*sw);
        }
        red[tid] = partial; __syncthreads();
        for (int s = 128; s > 0; s >>= 1){ if (tid < s) red[tid] += red[tid+s]; __syncthreads(); }
        if (tid == 0){
            float bias = (j < DSTATE) ? b_x[j] : b_dt[j-DSTATE];
            g_const[lp*NOUT + j] = red[0] + bias;
        }
    } else {
        // ---- ct_split
        float (*As)[65] = (float(*)[65])sh;
        float (*Bs)[65] = (float(*)[65])(sh + 4224);
        int b  = blk - 10752;
        int m0 = (b & 15)*64;
        int z  = b >> 4;
        int kbase = z * (DINNER/CTSPLIT);
        int tx = tid & 15, ty = tid >> 4;
        float acc[4][4];
        #pragma unroll
        for (int a=0;a<4;a++)
            #pragma unroll
            for (int c=0;c<4;c++) acc[a][c] = 0.f;

        for (int kk = 0; kk < DINNER/CTSPLIT; kk += 16){
            #pragma unroll
            for (int idx = tid; idx < 64*16; idx += 256){
                int m = idx >> 4, kq = idx & 15;
                As[kq][m] = Wout[(size_t)(m0+m)*DINNER + kbase + kk + kq];
            }
            #pragma unroll
            for (int idx = tid; idx < 64*16; idx += 256){
                int n = idx >> 4, kq = idx & 15;
                Bs[kq][n] = Dmat[(size_t)n*DINNER + kbase + kk + kq];
            }
            __syncthreads();
            #pragma unroll
            for (int i = 0; i < 16; i++){
                float af[4], bf[4];
                #pragma unroll
                for (int t2=0;t2<4;t2++) af[t2] = As[i][ty*4+t2];
                #pragma unroll
                for (int t2=0;t2<4;t2++) bf[t2] = Bs[i][tx*4+t2];
                #pragma unroll
                for (int a=0;a<4;a++)
                    #pragma unroll
                    for (int c=0;c<4;c++) acc[a][c] += af[a]*bf[c];
            }
            __syncthreads();
        }
        float* outp = g_Ctp + (size_t)z*DMODEL*DSTATE;
        #pragma unroll
        for (int a=0;a<4;a++)
            #pragma unroll
            for (int c=0;c<4;c++)
                outp[(size_t)(m0+ty*4+a)*DSTATE + tx*4 + c] = acc[a][c];
    }
}

// ======================= fused reduce kernel ===============================
// [0,2048): reduce_E (partials x2^20 -> E*4096 fp16 single = /256)
// [2048,2304): reduce_ct (-> Ct*1024 fp16 hi/lo)
__global__ __launch_bounds__(256)
void reduce_all(){
    const int blk = blockIdx.x;
    const int tid = threadIdx.x;
    if (blk < 2048){
        int i = blk*256 + tid;
        float s = 0.f;
        #pragma unroll
        for (int z = 0; z < ESPLIT; z++) s += g_Ep[(size_t)z*H4N*DMODEL + i];
        g_Ehf[i] = __float2half(s * (1.0f/256.0f));
    } else {
        int i = (blk - 2048)*256 + tid;
        float s = 0.f;
        #pragma unroll
        for (int z = 0; z < CTSPLIT; z++) s += g_Ctp[(size_t)z*DMODEL*DSTATE + i];
        float ss = s * 1024.0f;
        __half h, l; hf_split(ss, h, l);
        g_Cthf[i] = h; g_Ctlf[i] = l;
    }
}

// ======================= unified fp16 mma GEMM (NB B-passes) ===============
// C = A @ (Bh[+Bl])^T. A single fp16, B = NB fp16 operands, fp32 accum.
// BM=BN=128, BK=32, 8 warps (64x32). (1+NB) tiles/stage, double buffered.
// MODE 0: C += bias (if set), scaled by outScale. MODE 2: split-K partial.
#define MG_PITCH 80
#define MG_TILE  (128*MG_PITCH)       // 10240 B

__device__ __forceinline__ void mh_issue(uint32_t base, int NBtiles,
        const __half* __restrict__ A, const __half* __restrict__ Bh,
        const __half* __restrict__ Bl,
        int m0, int n0, int lda, int ldb, int kk, int tid){
    #pragma unroll
    for (int i = tid; i < 512; i += 256){
        int r = i >> 2, c = i & 3;
        uint32_t o = r*MG_PITCH + c*16;
        size_t ga = (size_t)(m0 + r)*lda + kk + c*8;
        size_t gb = (size_t)(n0 + r)*ldb + kk + c*8;
        cp16(base +           o, A  + ga);
        cp16(base + MG_TILE + o, Bh + gb);
        if (NBtiles == 2) cp16(base + 2*MG_TILE + o, Bl + gb);
    }
    cp_commit();
}

template<int MODE, int NB>
__global__ __launch_bounds__(256, 2)
void mma_fp16(const __half* __restrict__ A, const __half* __restrict__ Bh,
              const __half* __restrict__ Bl,
              float* __restrict__ C, const float* __restrict__ bias,
              int lda, int ldb, int kLen, int ldc, size_t sliceStride, float outScale){
    extern __shared__ __align__(16) char dsm[];
    const int STG = (1+NB)*MG_TILE;
    const int tid  = threadIdx.x;
    const int wid  = tid >> 5, lane = tid & 31;
    const int m0   = blockIdx.x * 128;
    const int n0   = blockIdx.y * 128;
    const int kbase= blockIdx.z * kLen;
    const int wm   = (wid >> 2) * 64;
    const int wn   = (wid & 3) * 32;
    const uint32_t sbu = smem_u32(dsm);
    const int NIT = kLen >> 5;

    float acc[4][4][4];
    #pragma unroll
    for (int a=0;a<4;a++)
        #pragma unroll
        for (int b=0;b<4;b++)
            #pragma unroll
            for (int c=0;c<4;c++) acc[a][b][c] = 0.f;

    mh_issue(sbu, NB, A, Bh, Bl, m0, n0, lda, ldb, kbase, tid);
    cp_wait0();
    __syncthreads();

    for (int t = 0; t < NIT; t++){
        int buf = t & 1;
        if (t + 1 < NIT)
            mh_issue(sbu + (buf^1)*STG, NB, A, Bh, Bl,
                     m0, n0, lda, ldb, kbase + (t+1)*32, tid);

        const uint32_t sb = sbu + buf*STG;
        #pragma unroll
        for (int ks = 0; ks < 2; ks++){
            uint32_t ah[4][4], bh[2][4], bl[2][4];
            #pragma unroll
            for (int mb = 0; mb < 4; mb++){
                int row = wm + mb*16 + (lane & 15);
                uint32_t o = row*MG_PITCH + ks*32 + (lane >> 4)*16;
                ldsm4(ah[mb], sb + o);
            }
            #pragma unroll
            for (int nb2 = 0; nb2 < 2; nb2++){
                int row = wn + nb2*16 + ((lane >> 3) & 1)*8 + (lane & 7);
                uint32_t o = row*MG_PITCH + ks*32 + (lane >> 4)*16;
                ldsm4(bh[nb2], sb + MG_TILE + o);
                if (NB == 2) ldsm4(bl[nb2], sb + 2*MG_TILE + o);
            }
            #pragma unroll
            for (int mb = 0; mb < 4; mb++)
                #pragma unroll
                for (int nb = 0; nb < 4; nb++){
                    int nb2 = nb >> 1, odd = nb & 1;
                    mma16816h(acc[mb][nb], ah[mb], bh[nb2][odd?1:0], bh[nb2][odd?3:2]);
                }
            if (NB == 2){
                #pragma unroll
                for (int mb = 0; mb < 4; mb++)
                    #pragma unroll
                    for (int nb = 0; nb < 4; nb++){
                        int nb2 = nb >> 1, odd = nb & 1;
                        mma16816h(acc[mb][nb], ah[mb], bl[nb2][odd?1:0], bl[nb2][odd?3:2]);
                    }
            }
        }

        if (t + 1 < NIT){ cp_wait0(); __syncthreads(); }
    }

    float* Co = (MODE == 2) ? (C + (size_t)blockIdx.z*sliceStride) : C;
    #pragma unroll
    for (int mb = 0; mb < 4; mb++){
        #pragma unroll
        for (int nb = 0; nb < 4; nb++){
            int r = m0 + wm + mb*16 + (lane >> 2);
            int c = n0 + wn + nb*8 + (lane & 3)*2;
            float2 v0 = make_float2(acc[mb][nb][0]*outScale, acc[mb][nb][1]*outScale);
            float2 v1 = make_float2(acc[mb][nb][2]*outScale, acc[mb][nb][3]*outScale);
            if (MODE == 0 && bias){
                float b0 = bias[c], b1 = bias[c+1];
                v0.x += b0; v0.y += b1;
                v1.x += b0; v1.y += b1;
            }
            *(float2*)&Co[(size_t)r*ldc + c]       = v0;
            *(float2*)&Co[(size_t)(r+8)*ldc + c]   = v1;
        }
    }
}

// ======================= combine (descale + shift-sum + SSM param) =========
__global__ __launch_bounds__(256)
void combine(const float* __restrict__ A_log){
    const int tid = threadIdx.x;
    const int m0  = blockIdx.x * 64;
    __shared__ float sG[64*130];
    #pragma unroll
    for (int it = 0; it < 32; it++){
        int i = tid + it*256;
        int r = i >> 7, j = i & 127;
        int m = m0 + r, l = m & (L_-1);
        int lp = l < 3 ? l : 3;
        float sum = 0.f;
        int kmin = (l >= 3) ? 0 : (3 - l);
        #pragma unroll
        for (int k = 0; k < 4; k++)
            if (k >= kmin) sum += g_H4[(size_t)(m-3+k)*H4N + k*128 + j];
        sG[r*130 + j] = g_const[lp*NOUT + j] + sum*INV_ESCALE;
    }
    __syncthreads();
    #pragma unroll
    for (int it = 0; it < 16; it++){
        int p = tid + it*256;
        int s = p >> 6;
        int r = p & 63;
        float xs = sG[r*130 + s];
        float dv = sG[r*130 + 64 + s];
        float dt = dv > 20.f ? dv : log1pf(expf(dv));
        float Aa = -expf(A_log[s]);
        float dA = expf(Aa*dt);
        float dBx = (1.f - dA)/Aa * xs;
        int m = m0 + r;
        int b = m >> 11;
        int l = m & (L_-1);
        size_t o = ((size_t)(b*DSTATE + s))*L_ + l;
        g_dA[o]  = dA;
        g_dBx[o] = dBx;
    }
}

// ======================= scan (fp16 zT output) =============================
__global__ __launch_bounds__(256)
void scan_kernel(){
    const int bs = blockIdx.x;
    const int t  = threadIdx.x;
    const size_t base = (size_t)bs * L_;
    float a[8], bb[8];
    #pragma unroll
    for (int i=0;i<8;i++){ a[i] = g_dA[base + t*8 + i]; bb[i] = g_dBx[base + t*8 + i]; }

    float Ai = 1.f, Bi = 0.f;
    #pragma unroll
    for (int i=0;i<8;i++){ Bi = Bi*a[i] + bb[i]; Ai *= a[i]; }

    const unsigned lane = t & 31, wid = t >> 5;
    #pragma unroll
    for (int off = 1; off < 32; off <<= 1){
        float Au = __shfl_up_sync(0xffffffffu, Ai, off);
        float Bu = __shfl_up_sync(0xffffffffu, Bi, off);
        if (lane >= off){ Bi = Ai*Bu + Bi; Ai = Ai*Au; }
    }
    __shared__ float wA[8], wB[8], pB[8];
    if (lane == 31){ wA[wid] = Ai; wB[wid] = Bi; }
    __syncthreads();
    if (t == 0){
        float cB = 0.f;
        #pragma unroll
        for (int w = 0; w < 8; w++){
            pB[w] = cB;
            cB = cB*wA[w] + wB[w];
        }
    }
    __syncthreads();
    float eA = __shfl_up_sync(0xffffffffu, Ai, 1);
    float eB = __shfl_up_sync(0xffffffffu, Bi, 1);
    if (lane == 0){ eA = 1.f; eB = 0.f; }
    float z = eA*pB[wid] + eB;

    __half hb[8];
    #pragma unroll
    for (int i = 0; i < 8; i++){
        z = a[i]*z + bb[i];
        hb[i] = __float2half(z);
    }
    *(uint4*)&g_zTf[base + t*8] = *(uint4*)hb;
}

// zT [b*64+s][l] -> z [m][s] fp16
__global__ __launch_bounds__(256)
void transpose_z(){
    __shared__ __half th[64][66];
    const int tid = threadIdx.x;
    const int l0  = blockIdx.x * 64;
    const int b   = blockIdx.y;
    #pragma unroll
    for (int it = 0; it < 16; it++){
        int i = tid + it*256;
        int s = i >> 6, lo = i & 63;
        th[s][lo] = g_zTf[(size_t)(b*DSTATE + s)*L_ + l0 + lo];
    }
    __syncthreads();
    #pragma unroll
    for (int it = 0; it < 16; it++){
        int i = tid + it*256;
        int l = i >> 6, s = i & 63;
        g_zf[(size_t)(b*L_ + l0 + l)*DSTATE + s] = th[s][l];
    }
}

// ======================= launch ============================================
extern "C" void kernel_launch(void* const* d_in, const int* in_sizes, int n_in,
                              void* d_out, int out_size){
    const float* x      = (const float*)d_in[0];
    const float* W_in   = (const float*)d_in[1];
    const float* b_in   = (const float*)d_in[2];
    const float* conv_w = (const float*)d_in[3];
    const float* conv_b = (const float*)d_in[4];
    const float* W_x    = (const float*)d_in[5];
    const float* b_x    = (const float*)d_in[6];
    const float* W_dt   = (const float*)d_in[7];
    const float* b_dt   = (const float*)d_in[8];
    const float* A_log  = (const float*)d_in[9];
    const float* D_mat  = (const float*)d_in[10];
    const float* W_out  = (const float*)d_in[11];
    const float* b_out  = (const float*)d_in[12];
    float* out = (float*)d_out;

    cudaFuncSetAttribute(mma_fp16<0,1>, cudaFuncAttributeMaxDynamicSharedMemorySize, 2*2*MG_TILE);
    cudaFuncSetAttribute(mma_fp16<0,2>, cudaFuncAttributeMaxDynamicSharedMemorySize, 2*3*MG_TILE);
    cudaFuncSetAttribute(mma_fp16<2,2>, cudaFuncAttributeMaxDynamicSharedMemorySize, 2*3*MG_TILE);

    float *pEp, *pH4;
    cudaGetSymbolAddress((void**)&pEp, g_Ep);
    cudaGetSymbolAddress((void**)&pH4, g_H4);
    __half *pAbf, *pWTh, *pWTl, *pEh, *pXh, *pZf, *pCth, *pCtl;
    cudaGetSymbolAddress((void**)&pAbf, g_Abf);
    cudaGetSymbolAddress((void**)&pWTh, g_WTh);
    cudaGetSymbolAddress((void**)&pWTl, g_WTl);
    cudaGetSymbolAddress((void**)&pEh,  g_Ehf);
    cudaGetSymbolAddress((void**)&pXh,  g_Xh);
    cudaGetSymbolAddress((void**)&pZf,  g_zf);
    cudaGetSymbolAddress((void**)&pCth, g_Cthf);
    cudaGetSymbolAddress((void**)&pCtl, g_Ctlf);

    // 1. all independent prep + ct GEMM in one wave
    prep_all<<<PREP_BLOCKS, 256>>>(x, W_in, conv_w, conv_b,
                                   W_x, b_x, W_dt, b_dt, b_in, W_out, D_mat);

    // 2. E partials = (Abig*1024) @ (Win^T*1024)^T  (2-pass fp16, split-K=4)
    mma_fp16<2,2><<<dim3(H4N/128, DMODEL/128, ESPLIT), 256, 2*3*MG_TILE>>>(
        pAbf, pWTh, pWTl, pEp, nullptr,
        DINNER, DINNER, DINNER/ESPLIT, DMODEL, (size_t)H4N*DMODEL, 1.0f);

    // 3. reduce_E (/256 -> E*4096 fp16 single) + reduce_ct (*1024 hi/lo)
    reduce_all<<<2048 + 256, 256>>>();

    // 4. H4 = fp16(X) @ (E*4096)^T  (1-pass fp16)
    mma_fp16<0,1><<<dim3(MTOT/128, H4N/128, 1), 256, 2*2*MG_TILE>>>(
        pXh, pEh, nullptr, pH4, nullptr,
        DMODEL, DMODEL, DMODEL, H4N, 0, 1.0f);

    // 5-7. combine (descale), scan (fp16 z), transpose
    combine<<<MTOT/64, 256>>>(A_log);
    scan_kernel<<<B_*DSTATE, 256>>>();
    transpose_z<<<dim3(L_/64, B_), 256>>>();

    // 8. out = z @ (Ct*1024)^T / 1024 + b_out  (2-pass fp16)
    mma_fp16<0,2><<<dim3(MTOT/128, DMODEL/128, 1), 256, 2*3*MG_TILE>>>(
        pZf, pCth, pCtl, out, b_out,
        DSTATE, DSTATE, DSTATE, DMODEL, 0, 9.765625e-4f);
}

// round 16
// speedup vs baseline: 1.6900x; 1.0604x over previous
#include <cuda_runtime.h>
#include <cuda_bf16.h>
#include <cuda_fp16.h>
#include <math.h>
#include <stdint.h>

#define B_      4
#define L_      2048
#define DMODEL  1024
#define DINNER  2048
#define DSTATE  64
#define KCONV   4
#define MTOT    (B_*L_)     // 8192
#define NOUT    128         // 2*DSTATE (x_ssm | dt)
#define CTSPLIT 16
#define ESPLIT  4
#define H4N     512         // 4*NOUT rows of Eall
#define INV_ESCALE  2.44140625e-4f     // 1/4096 (H4 carries x_ssm*4096)

// ---------------- scratch (device globals: no allocation allowed) ----------
__device__ float g_const[4*NOUT];
__device__ float g_Ctp[CTSPLIT*DMODEL*DSTATE];
__device__ __align__(16) __half g_Ctf[DMODEL*DSTATE];         // Ct*1024 fp16
__device__ float g_Ep[ESPLIT*H4N*DMODEL];                     // partials (x 2^20)
__device__ __align__(16) __half g_Ehf[H4N*DMODEL];            // E*4096 fp16
__device__ __align__(16) __half g_Abf[H4N*DINNER];            // Abig*1024 fp16
__device__ __align__(16) __half g_WTf[DMODEL*DINNER];         // Win^T*1024 fp16
__device__ __align__(16) __half g_Xh[(size_t)MTOT*DMODEL];    // fp16(x)
__device__ __align__(16) __half g_zTf[B_*DSTATE*L_];          // z [b*64+s][l] fp16
__device__ __align__(16) __half g_zf[MTOT*DSTATE];            // z [m][s] fp16
__device__ __align__(16) float g_H4[(size_t)MTOT*H4N];
__device__ float g_dA[B_*DSTATE*L_];
__device__ float g_dBx[B_*DSTATE*L_];

// ======================= helpers ===========================================
__device__ __forceinline__ uint32_t smem_u32(const void* p){
    uint32_t a;
    asm("{ .reg .u64 t; cvta.to.shared.u64 t, %1; cvt.u32.u64 %0, t; }" : "=r"(a) : "l"(p));
    return a;
}
__device__ __forceinline__ void cp16(uint32_t saddr, const void* g){
    asm volatile("cp.async.ca.shared.global [%0], [%1], 16;" :: "r"(saddr), "l"(g));
}
__device__ __forceinline__ void cp_commit(){ asm volatile("cp.async.commit_group;"); }
__device__ __forceinline__ void cp_wait0(){ asm volatile("cp.async.wait_group 0;"); }

__device__ __forceinline__ void ldsm4(uint32_t* r, uint32_t addr){
    asm volatile("ldmatrix.sync.aligned.m8n8.x4.shared.b16 {%0,%1,%2,%3}, [%4];"
        : "=r"(r[0]), "=r"(r[1]), "=r"(r[2]), "=r"(r[3]) : "r"(addr));
}
__device__ __forceinline__ void mma16816h(float* d, const uint32_t* a, uint32_t b0, uint32_t b1){
    asm volatile("mma.sync.aligned.m16n8k16.row.col.f32.f16.f16.f32 "
        "{%0,%1,%2,%3}, {%4,%5,%6,%7}, {%8,%9}, {%0,%1,%2,%3};"
        : "+f"(d[0]), "+f"(d[1]), "+f"(d[2]), "+f"(d[3])
        : "r"(a[0]), "r"(a[1]), "r"(a[2]), "r"(a[3]), "r"(b0), "r"(b1));
}

// ======================= fused prep mega-kernel ============================
// Roles: [0,4096) absplit(fp16 x1024) | [4096,6144) wT(fp16 x1024)
//        [6144,10240) xsplit(fp16) | [10240,10752) const | [10752,11008) ct_split
#define PREP_BLOCKS (4096 + 2048 + 4096 + 512 + 256)

__global__ __launch_bounds__(256)
void prep_all(const float* __restrict__ x,    const float* __restrict__ Win,
              const float* __restrict__ convw, const float* __restrict__ convb,
              const float* __restrict__ Wx,   const float* __restrict__ b_x,
              const float* __restrict__ Wdt,  const float* __restrict__ b_dt,
              const float* __restrict__ b_in,
              const float* __restrict__ Wout, const float* __restrict__ Dmat){
    __shared__ __align__(16) char sh[8448];
    const int blk = blockIdx.x;
    const int tid = threadIdx.x;

    if (blk < 4096){
        // ---- absplit: Abig*1024 -> fp16 single
        int idx = blk*256 + tid;
        int c   = idx & (DINNER-1);
        int row = idx >> 11;
        int k4  = row >> 7, j = row & 127;
        float p = (j < DSTATE) ? Wx[j*DINNER + c] : Wdt[(j-DSTATE)*DINNER + c];
        float v = p * convw[c*KCONV + k4] * 1024.0f;
        g_Abf[idx] = __float2half(v);
    } else if (blk < 6144){
        // ---- wT: Win [c][dm] -> [dm][c] fp16 x1024 single
        float (*t)[33] = (float(*)[33])sh;
        int b  = blk - 4096;
        int n0 = (b & 31)*32;
        int k0 = (b >> 5)*32;
        int tx = tid & 31, ty = tid >> 5;
        #pragma unroll
        for (int p = 0; p < 4; p++){
            int k = ty + p*8;
            t[k][tx] = Win[(size_t)(k0+k)*DMODEL + n0 + tx];
        }
        __syncthreads();
        #pragma unroll
        for (int p = 0; p < 4; p++){
            int n = ty + p*8;
            g_WTf[(size_t)(n0+n)*DINNER + k0 + tx] = __float2half(t[tx][n] * 1024.0f);
        }
    } else if (blk < 10240){
        // ---- xsplit: fp16 single (8 floats per thread)
        size_t i = ((size_t)(blk - 6144)*256 + tid)*8;
        float4 v0 = *(const float4*)&x[i];
        float4 v1 = *(const float4*)&x[i+4];
        __half h[8];
        h[0]=__float2half(v0.x); h[1]=__float2half(v0.y);
        h[2]=__float2half(v0.z); h[3]=__float2half(v0.w);
        h[4]=__float2half(v1.x); h[5]=__float2half(v1.y);
        h[6]=__float2half(v1.z); h[7]=__float2half(v1.w);
        *(uint4*)&g_Xh[i] = *(uint4*)h;
    } else if (blk < 10752){
        // ---- const
        float* red = (float*)sh;
        int b  = blk - 10240;
        int j  = b & 127;
        int lp = b >> 7;
        int kstart = 3 - lp;
        float partial = 0.f;
        for (int c = tid; c < DINNER; c += 256){
            float sw = 0.f;
            #pragma unroll
            for (int k = 0; k < 4; k++) if (k >= kstart) sw += convw[c*4 + k];
            float p = (j < DSTATE) ? Wx[j*DINNER + c] : Wdt[(j-DSTATE)*DINNER + c];
            partial += p * (convb[c] + b_in[c]*sw);
        }
        red[tid] = partial; __syncthreads();
        for (int s = 128; s > 0; s >>= 1){ if (tid < s) red[tid] += red[tid+s]; __syncthreads(); }
        if (tid == 0){
            float bias = (j < DSTATE) ? b_x[j] : b_dt[j-DSTATE];
            g_const[lp*NOUT + j] = red[0] + bias;
        }
    } else {
        // ---- ct_split
        float (*As)[65] = (float(*)[65])sh;
        float (*Bs)[65] = (float(*)[65])(sh + 4224);
        int b  = blk - 10752;
        int m0 = (b & 15)*64;
        int z  = b >> 4;
        int kbase = z * (DINNER/CTSPLIT);
        int tx = tid & 15, ty = tid >> 4;
        float acc[4][4];
        #pragma unroll
        for (int a=0;a<4;a++)
            #pragma unroll
            for (int c=0;c<4;c++) acc[a][c] = 0.f;

        for (int kk = 0; kk < DINNER/CTSPLIT; kk += 16){
            #pragma unroll
            for (int idx = tid; idx < 64*16; idx += 256){
                int m = idx >> 4, kq = idx & 15;
                As[kq][m] = Wout[(size_t)(m0+m)*DINNER + kbase + kk + kq];
            }
            #pragma unroll
            for (int idx = tid; idx < 64*16; idx += 256){
                int n = idx >> 4, kq = idx & 15;
                Bs[kq][n] = Dmat[(size_t)n*DINNER + kbase + kk + kq];
            }
            __syncthreads();
            #pragma unroll
            for (int i = 0; i < 16; i++){
                float af[4], bf[4];
                #pragma unroll
                for (int t2=0;t2<4;t2++) af[t2] = As[i][ty*4+t2];
                #pragma unroll
                for (int t2=0;t2<4;t2++) bf[t2] = Bs[i][tx*4+t2];
                #pragma unroll
                for (int a=0;a<4;a++)
                    #pragma unroll
                    for (int c=0;c<4;c++) acc[a][c] += af[a]*bf[c];
            }
            __syncthreads();
        }
        float* outp = g_Ctp + (size_t)z*DMODEL*DSTATE;
        #pragma unroll
        for (int a=0;a<4;a++)
            #pragma unroll
            for (int c=0;c<4;c++)
                outp[(size_t)(m0+ty*4+a)*DSTATE + tx*4 + c] = acc[a][c];
    }
}

// ======================= fused reduce kernel ===============================
// [0,2048): reduce_E (partials x2^20 -> E*4096 fp16 = /256)
// [2048,2304): reduce_ct (-> Ct*1024 fp16)
__global__ __launch_bounds__(256)
void reduce_all(){
    const int blk = blockIdx.x;
    const int tid = threadIdx.x;
    if (blk < 2048){
        int i = blk*256 + tid;
        float s = 0.f;
        #pragma unroll
        for (int z = 0; z < ESPLIT; z++) s += g_Ep[(size_t)z*H4N*DMODEL + i];
        g_Ehf[i] = __float2half(s * (1.0f/256.0f));
    } else {
        int i = (blk - 2048)*256 + tid;
        float s = 0.f;
        #pragma unroll
        for (int z = 0; z < CTSPLIT; z++) s += g_Ctp[(size_t)z*DMODEL*DSTATE + i];
        g_Ctf[i] = __float2half(s * 1024.0f);
    }
}

// ======================= unified 1-pass fp16 mma GEMM ======================
// C = A @ B^T. Both operands single fp16, fp32 accum.
// BM=BN=128, BK=32, 8 warps (64x32). 2 tiles/stage, double buffered (40KB).
// MODE 0: C += bias (if set), scaled by outScale. MODE 2: split-K partial.
#define MG_PITCH 80
#define MG_TILE  (128*MG_PITCH)       // 10240 B
#define MH_STG   (2*MG_TILE)          // 20480 B
#define MH_SMEM  (2*MH_STG)           // 40960 B

__device__ __forceinline__ void mh_issue(uint32_t base,
        const __half* __restrict__ A, const __half* __restrict__ Bm,
        int m0, int n0, int lda, int ldb, int kk, int tid){
    #pragma unroll
    for (int i = tid; i < 512; i += 256){
        int r = i >> 2, c = i & 3;
        uint32_t o = r*MG_PITCH + c*16;
        cp16(base +           o, A  + (size_t)(m0 + r)*lda + kk + c*8);
        cp16(base + MG_TILE + o, Bm + (size_t)(n0 + r)*ldb + kk + c*8);
    }
    cp_commit();
}

template<int MODE>
__global__ __launch_bounds__(256, 2)
void mma_fp16(const __half* __restrict__ A, const __half* __restrict__ Bm,
              float* __restrict__ C, const float* __restrict__ bias,
              int lda, int ldb, int kLen, int ldc, size_t sliceStride, float outScale){
    extern __shared__ __align__(16) char dsm[];
    const int tid  = threadIdx.x;
    const int wid  = tid >> 5, lane = tid & 31;
    const int m0   = blockIdx.x * 128;
    const int n0   = blockIdx.y * 128;
    const int kbase= blockIdx.z * kLen;
    const int wm   = (wid >> 2) * 64;
    const int wn   = (wid & 3) * 32;
    const uint32_t sbu = smem_u32(dsm);
    const int NIT = kLen >> 5;

    float acc[4][4][4];
    #pragma unroll
    for (int a=0;a<4;a++)
        #pragma unroll
        for (int b=0;b<4;b++)
            #pragma unroll
            for (int c=0;c<4;c++) acc[a][b][c] = 0.f;

    mh_issue(sbu, A, Bm, m0, n0, lda, ldb, kbase, tid);
    cp_wait0();
    __syncthreads();

    for (int t = 0; t < NIT; t++){
        int buf = t & 1;
        if (t + 1 < NIT)
            mh_issue(sbu + (buf^1)*MH_STG, A, Bm,
                     m0, n0, lda, ldb, kbase + (t+1)*32, tid);

        const uint32_t sb = sbu + buf*MH_STG;
        #pragma unroll
        for (int ks = 0; ks < 2; ks++){
            uint32_t ah[4][4], bh[2][4];
            #pragma unroll
            for (int mb = 0; mb < 4; mb++){
                int row = wm + mb*16 + (lane & 15);
                uint32_t o = row*MG_PITCH + ks*32 + (lane >> 4)*16;
                ldsm4(ah[mb], sb + o);
            }
            #pragma unroll
            for (int nb2 = 0; nb2 < 2; nb2++){
                int row = wn + nb2*16 + ((lane >> 3) & 1)*8 + (lane & 7);
                uint32_t o = row*MG_PITCH + ks*32 + (lane >> 4)*16;
                ldsm4(bh[nb2], sb + MG_TILE + o);
            }
            #pragma unroll
            for (int mb = 0; mb < 4; mb++)
                #pragma unroll
                for (int nb = 0; nb < 4; nb++){
                    int nb2 = nb >> 1, odd = nb & 1;
                    mma16816h(acc[mb][nb], ah[mb], bh[nb2][odd?1:0], bh[nb2][odd?3:2]);
                }
        }

        if (t + 1 < NIT){ cp_wait0(); __syncthreads(); }
    }

    float* Co = (MODE == 2) ? (C + (size_t)blockIdx.z*sliceStride) : C;
    #pragma unroll
    for (int mb = 0; mb < 4; mb++){
        #pragma unroll
        for (int nb = 0; nb < 4; nb++){
            int r = m0 + wm + mb*16 + (lane >> 2);
            int c = n0 + wn + nb*8 + (lane & 3)*2;
            float2 v0 = make_float2(acc[mb][nb][0]*outScale, acc[mb][nb][1]*outScale);
            float2 v1 = make_float2(acc[mb][nb][2]*outScale, acc[mb][nb][3]*outScale);
            if (MODE == 0 && bias){
                float b0 = bias[c], b1 = bias[c+1];
                v0.x += b0; v0.y += b1;
                v1.x += b0; v1.y += b1;
            }
            *(float2*)&Co[(size_t)r*ldc + c]       = v0;
            *(float2*)&Co[(size_t)(r+8)*ldc + c]   = v1;
        }
    }
}

// ======================= combine (descale + shift-sum + SSM param) =========
__global__ __launch_bounds__(256)
void combine(const float* __restrict__ A_log){
    const int tid = threadIdx.x;
    const int m0  = blockIdx.x * 64;
    __shared__ float sG[64*130];
    #pragma unroll
    for (int it = 0; it < 32; it++){
        int i = tid + it*256;
        int r = i >> 7, j = i & 127;
        int m = m0 + r, l = m & (L_-1);
        int lp = l < 3 ? l : 3;
        float sum = 0.f;
        int kmin = (l >= 3) ? 0 : (3 - l);
        #pragma unroll
        for (int k = 0; k < 4; k++)
            if (k >= kmin) sum += g_H4[(size_t)(m-3+k)*H4N + k*128 + j];
        sG[r*130 + j] = g_const[lp*NOUT + j] + sum*INV_ESCALE;
    }
    __syncthreads();
    #pragma unroll
    for (int it = 0; it < 16; it++){
        int p = tid + it*256;
        int s = p >> 6;
        int r = p & 63;
        float xs = sG[r*130 + s];
        float dv = sG[r*130 + 64 + s];
        float dt = dv > 20.f ? dv : log1pf(expf(dv));
        float Aa = -expf(A_log[s]);
        float dA = expf(Aa*dt);
        float dBx = (1.f - dA)/Aa * xs;
        int m = m0 + r;
        int b = m >> 11;
        int l = m & (L_-1);
        size_t o = ((size_t)(b*DSTATE + s))*L_ + l;
        g_dA[o]  = dA;
        g_dBx[o] = dBx;
    }
}

// ======================= scan (fp16 zT output) =============================
__global__ __launch_bounds__(256)
void scan_kernel(){
    const int bs = blockIdx.x;
    const int t  = threadIdx.x;
    const size_t base = (size_t)bs * L_;
    float a[8], bb[8];
    #pragma unroll
    for (int i=0;i<8;i++){ a[i] = g_dA[base + t*8 + i]; bb[i] = g_dBx[base + t*8 + i]; }

    float Ai = 1.f, Bi = 0.f;
    #pragma unroll
    for (int i=0;i<8;i++){ Bi = Bi*a[i] + bb[i]; Ai *= a[i]; }

    const unsigned lane = t & 31, wid = t >> 5;
    #pragma unroll
    for (int off = 1; off < 32; off <<= 1){
        float Au = __shfl_up_sync(0xffffffffu, Ai, off);
        float Bu = __shfl_up_sync(0xffffffffu, Bi, off);
        if (lane >= off){ Bi = Ai*Bu + Bi; Ai = Ai*Au; }
    }
    __shared__ float wA[8], wB[8], pB[8];
    if (lane == 31){ wA[wid] = Ai; wB[wid] = Bi; }
    __syncthreads();
    if (t == 0){
        float cB = 0.f;
        #pragma unroll
        for (int w = 0; w < 8; w++){
            pB[w] = cB;
            cB = cB*wA[w] + wB[w];
        }
    }
    __syncthreads();
    float eA = __shfl_up_sync(0xffffffffu, Ai, 1);
    float eB = __shfl_up_sync(0xffffffffu, Bi, 1);
    if (lane == 0){ eA = 1.f; eB = 0.f; }
    float z = eA*pB[wid] + eB;

    __half hb[8];
    #pragma unroll
    for (int i = 0; i < 8; i++){
        z = a[i]*z + bb[i];
        hb[i] = __float2half(z);
    }
    *(uint4*)&g_zTf[base + t*8] = *(uint4*)hb;
}

// zT [b*64+s][l] -> z [m][s] fp16
__global__ __launch_bounds__(256)
void transpose_z(){
    __shared__ __half th[64][66];
    const int tid = threadIdx.x;
    const int l0  = blockIdx.x * 64;
    const int b   = blockIdx.y;
    #pragma unroll
    for (int it = 0; it < 16; it++){
        int i = tid + it*256;
        int s = i >> 6, lo = i & 63;
        th[s][lo] = g_zTf[(size_t)(b*DSTATE + s)*L_ + l0 + lo];
    }
    __syncthreads();
    #pragma unroll
    for (int it = 0; it < 16; it++){
        int i = tid + it*256;
        int l = i >> 6, s = i & 63;
        g_zf[(size_t)(b*L_ + l0 + l)*DSTATE + s] = th[s][l];
    }
}

// ======================= launch ============================================
extern "C" void kernel_launch(void* const* d_in, const int* in_sizes, int n_in,
                              void* d_out, int out_size){
    const float* x      = (const float*)d_in[0];
    const float* W_in   = (const float*)d_in[1];
    const float* b_in   = (const float*)d_in[2];
    const float* conv_w = (const float*)d_in[3];
    const float* conv_b = (const float*)d_in[4];
    const float* W_x    = (const float*)d_in[5];
    const float* b_x    = (const float*)d_in[6];
    const float* W_dt   = (const float*)d_in[7];
    const float* b_dt   = (const float*)d_in[8];
    const float* A_log  = (const float*)d_in[9];
    const float* D_mat  = (const float*)d_in[10];
    const float* W_out  = (const float*)d_in[11];
    const float* b_out  = (const float*)d_in[12];
    float* out = (float*)d_out;

    cudaFuncSetAttribute(mma_fp16<0>, cudaFuncAttributeMaxDynamicSharedMemorySize, MH_SMEM);
    cudaFuncSetAttribute(mma_fp16<2>, cudaFuncAttributeMaxDynamicSharedMemorySize, MH_SMEM);

    float *pEp, *pH4;
    cudaGetSymbolAddress((void**)&pEp, g_Ep);
    cudaGetSymbolAddress((void**)&pH4, g_H4);
    __half *pAbf, *pWTf, *pEh, *pXh, *pZf, *pCtf;
    cudaGetSymbolAddress((void**)&pAbf, g_Abf);
    cudaGetSymbolAddress((void**)&pWTf, g_WTf);
    cudaGetSymbolAddress((void**)&pEh,  g_Ehf);
    cudaGetSymbolAddress((void**)&pXh,  g_Xh);
    cudaGetSymbolAddress((void**)&pZf,  g_zf);
    cudaGetSymbolAddress((void**)&pCtf, g_Ctf);

    // 1. all independent prep + ct GEMM in one wave
    prep_all<<<PREP_BLOCKS, 256>>>(x, W_in, conv_w, conv_b,
                                   W_x, b_x, W_dt, b_dt, b_in, W_out, D_mat);

    // 2. E partials = (Abig*1024) @ (Win^T*1024)^T  (1-pass fp16, split-K=4)
    mma_fp16<2><<<dim3(H4N/128, DMODEL/128, ESPLIT), 256, MH_SMEM>>>(
        pAbf, pWTf, pEp, nullptr,
        DINNER, DINNER, DINNER/ESPLIT, DMODEL, (size_t)H4N*DMODEL, 1.0f);

    // 3. reduce_E (/256 -> E*4096 fp16) + reduce_ct (*1024 fp16)
    reduce_all<<<2048 + 256, 256>>>();

    // 4. H4 = fp16(X) @ (E*4096)^T  (1-pass fp16)
    mma_fp16<0><<<dim3(MTOT/128, H4N/128, 1), 256, MH_SMEM>>>(
        pXh, pEh, pH4, nullptr,
        DMODEL, DMODEL, DMODEL, H4N, 0, 1.0f);

    // 5-7. combine (descale), scan (fp16 z), transpose
    combine<<<MTOT/64, 256>>>(A_log);
    scan_kernel<<<B_*DSTATE, 256>>>();
    transpose_z<<<dim3(L_/64, B_), 256>>>();

    // 8. out = z @ (Ct*1024)^T / 1024 + b_out  (1-pass fp16)
    mma_fp16<0><<<dim3(MTOT/128, DMODEL/128, 1), 256, MH_SMEM>>>(
        pZf, pCtf, out, b_out,
        DSTATE, DSTATE, DSTATE, DMODEL, 0, 9.765625e-4f);
}

// round 17
// speedup vs baseline: 1.7424x; 1.0310x over previous
#include <cuda_runtime.h>
#include <cuda_bf16.h>
#include <cuda_fp16.h>
#include <math.h>
#include <stdint.h>

#define B_      4
#define L_      2048
#define DMODEL  1024
#define DINNER  2048
#define DSTATE  64
#define KCONV   4
#define MTOT    (B_*L_)     // 8192
#define NOUT    128         // 2*DSTATE (x_ssm | dt)
#define CTSPLIT 16
#define ESPLIT  4
#define H4N     512         // 4*NOUT rows of Eall
#define INV_ESCALE  2.44140625e-4f     // 1/4096 (H4 carries x_ssm*4096)

// ---------------- scratch (device globals: no allocation allowed) ----------
__device__ float g_const[4*NOUT];
__device__ float g_Ctp[CTSPLIT*DMODEL*DSTATE];
__device__ __align__(16) __half g_Ctf[DMODEL*DSTATE];         // Ct*1024 fp16
__device__ float g_Ep[ESPLIT*H4N*DMODEL];                     // partials (x 2^20)
__device__ __align__(16) __half g_Ehf[H4N*DMODEL];            // E*4096 fp16
__device__ __align__(16) __half g_Abf[H4N*DINNER];            // Abig*1024 fp16
__device__ __align__(16) __half g_WTf[DMODEL*DINNER];         // Win^T*1024 fp16
__device__ __align__(16) __half g_Xh[(size_t)MTOT*DMODEL];    // fp16(x)
__device__ __align__(16) __half g_zTf[B_*DSTATE*L_];          // z [b*64+s][l] fp16
__device__ __align__(16) float g_H4[(size_t)MTOT*H4N];
__device__ float g_dA[B_*DSTATE*L_];
__device__ float g_dBx[B_*DSTATE*L_];

// ======================= helpers ===========================================
__device__ __forceinline__ uint32_t smem_u32(const void* p){
    uint32_t a;
    asm("{ .reg .u64 t; cvta.to.shared.u64 t, %1; cvt.u32.u64 %0, t; }" : "=r"(a) : "l"(p));
    return a;
}
__device__ __forceinline__ void cp16(uint32_t saddr, const void* g){
    asm volatile("cp.async.ca.shared.global [%0], [%1], 16;" :: "r"(saddr), "l"(g));
}
__device__ __forceinline__ void cp_commit(){ asm volatile("cp.async.commit_group;"); }
__device__ __forceinline__ void cp_wait0(){ asm volatile("cp.async.wait_group 0;"); }

__device__ __forceinline__ void ldsm4(uint32_t* r, uint32_t addr){
    asm volatile("ldmatrix.sync.aligned.m8n8.x4.shared.b16 {%0,%1,%2,%3}, [%4];"
        : "=r"(r[0]), "=r"(r[1]), "=r"(r[2]), "=r"(r[3]) : "r"(addr));
}
__device__ __forceinline__ void ldsm4t(uint32_t* r, uint32_t addr){
    asm volatile("ldmatrix.sync.aligned.m8n8.x4.trans.shared.b16 {%0,%1,%2,%3}, [%4];"
        : "=r"(r[0]), "=r"(r[1]), "=r"(r[2]), "=r"(r[3]) : "r"(addr));
}
__device__ __forceinline__ void mma16816h(float* d, const uint32_t* a, uint32_t b0, uint32_t b1){
    asm volatile("mma.sync.aligned.m16n8k16.row.col.f32.f16.f16.f32 "
        "{%0,%1,%2,%3}, {%4,%5,%6,%7}, {%8,%9}, {%0,%1,%2,%3};"
        : "+f"(d[0]), "+f"(d[1]), "+f"(d[2]), "+f"(d[3])
        : "r"(a[0]), "r"(a[1]), "r"(a[2]), "r"(a[3]), "r"(b0), "r"(b1));
}

// ======================= fused prep mega-kernel ============================
// Roles: [0,4096) absplit(fp16 x1024) | [4096,6144) wT(fp16 x1024)
//        [6144,10240) xsplit(fp16) | [10240,10752) const | [10752,11008) ct_split
#define PREP_BLOCKS (4096 + 2048 + 4096 + 512 + 256)

__global__ __launch_bounds__(256)
void prep_all(const float* __restrict__ x,    const float* __restrict__ Win,
              const float* __restrict__ convw, const float* __restrict__ convb,
              const float* __restrict__ Wx,   const float* __restrict__ b_x,
              const float* __restrict__ Wdt,  const float* __restrict__ b_dt,
              const float* __restrict__ b_in,
              const float* __restrict__ Wout, const float* __restrict__ Dmat){
    __shared__ __align__(16) char sh[8448];
    const int blk = blockIdx.x;
    const int tid = threadIdx.x;

    if (blk < 4096){
        int idx = blk*256 + tid;
        int c   = idx & (DINNER-1);
        int row = idx >> 11;
        int k4  = row >> 7, j = row & 127;
        float p = (j < DSTATE) ? Wx[j*DINNER + c] : Wdt[(j-DSTATE)*DINNER + c];
        g_Abf[idx] = __float2half(p * convw[c*KCONV + k4] * 1024.0f);
    } else if (blk < 6144){
        float (*t)[33] = (float(*)[33])sh;
        int b  = blk - 4096;
        int n0 = (b & 31)*32;
        int k0 = (b >> 5)*32;
        int tx = tid & 31, ty = tid >> 5;
        #pragma unroll
        for (int p = 0; p < 4; p++){
            int k = ty + p*8;
            t[k][tx] = Win[(size_t)(k0+k)*DMODEL + n0 + tx];
        }
        __syncthreads();
        #pragma unroll
        for (int p = 0; p < 4; p++){
            int n = ty + p*8;
            g_WTf[(size_t)(n0+n)*DINNER + k0 + tx] = __float2half(t[tx][n] * 1024.0f);
        }
    } else if (blk < 10240){
        size_t i = ((size_t)(blk - 6144)*256 + tid)*8;
        float4 v0 = *(const float4*)&x[i];
        float4 v1 = *(const float4*)&x[i+4];
        __half h[8];
        h[0]=__float2half(v0.x); h[1]=__float2half(v0.y);
        h[2]=__float2half(v0.z); h[3]=__float2half(v0.w);
        h[4]=__float2half(v1.x); h[5]=__float2half(v1.y);
        h[6]=__float2half(v1.z); h[7]=__float2half(v1.w);
        *(uint4*)&g_Xh[i] = *(uint4*)h;
    } else if (blk < 10752){
        float* red = (float*)sh;
        int b  = blk - 10240;
        int j  = b & 127;
        int lp = b >> 7;
        int kstart = 3 - lp;
        float partial = 0.f;
        for (int c = tid; c < DINNER; c += 256){
            float sw = 0.f;
            #pragma unroll
            for (int k = 0; k < 4; k++) if (k >= kstart) sw += convw[c*4 + k];
            float p = (j < DSTATE) ? Wx[j*DINNER + c] : Wdt[(j-DSTATE)*DINNER + c];
            partial += p * (convb[c] + b_in[c]*sw);
        }
        red[tid] = partial; __syncthreads();
        for (int s = 128; s > 0; s >>= 1){ if (tid < s) red[tid] += red[tid+s]; __syncthreads(); }
        if (tid == 0){
            float bias = (j < DSTATE) ? b_x[j] : b_dt[j-DSTATE];
            g_const[lp*NOUT + j] = red[0] + bias;
        }
    } else {
        float (*As)[65] = (float(*)[65])sh;
        float (*Bs)[65] = (float(*)[65])(sh + 4224);
        int b  = blk - 10752;
        int m0 = (b & 15)*64;
        int z  = b >> 4;
        int kbase = z * (DINNER/CTSPLIT);
        int tx = tid & 15, ty = tid >> 4;
        float acc[4][4];
        #pragma unroll
        for (int a=0;a<4;a++)
            #pragma unroll
            for (int c=0;c<4;c++) acc[a][c] = 0.f;

        for (int kk = 0; kk < DINNER/CTSPLIT; kk += 16){
            #pragma unroll
            for (int idx = tid; idx < 64*16; idx += 256){
                int m = idx >> 4, kq = idx & 15;
                As[kq][m] = Wout[(size_t)(m0+m)*DINNER + kbase + kk + kq];
            }
            #pragma unroll
            for (int idx = tid; idx < 64*16; idx += 256){
                int n = idx >> 4, kq = idx & 15;
                Bs[kq][n] = Dmat[(size_t)n*DINNER + kbase + kk + kq];
            }
            __syncthreads();
            #pragma unroll
            for (int i = 0; i < 16; i++){
                float af[4], bf[4];
                #pragma unroll
                for (int t2=0;t2<4;t2++) af[t2] = As[i][ty*4+t2];
                #pragma unroll
                for (int t2=0;t2<4;t2++) bf[t2] = Bs[i][tx*4+t2];
                #pragma unroll
                for (int a=0;a<4;a++)
                    #pragma unroll
                    for (int c=0;c<4;c++) acc[a][c] += af[a]*bf[c];
            }
            __syncthreads();
        }
        float* outp = g_Ctp + (size_t)z*DMODEL*DSTATE;
        #pragma unroll
        for (int a=0;a<4;a++)
            #pragma unroll
            for (int c=0;c<4;c++)
                outp[(size_t)(m0+ty*4+a)*DSTATE + tx*4 + c] = acc[a][c];
    }
}

// ======================= fused reduce kernel ===============================
__global__ __launch_bounds__(256)
void reduce_all(){
    const int blk = blockIdx.x;
    const int tid = threadIdx.x;
    if (blk < 2048){
        int i = blk*256 + tid;
        float s = 0.f;
        #pragma unroll
        for (int z = 0; z < ESPLIT; z++) s += g_Ep[(size_t)z*H4N*DMODEL + i];
        g_Ehf[i] = __float2half(s * (1.0f/256.0f));
    } else {
        int i = (blk - 2048)*256 + tid;
        float s = 0.f;
        #pragma unroll
        for (int z = 0; z < CTSPLIT; z++) s += g_Ctp[(size_t)z*DMODEL*DSTATE + i];
        g_Ctf[i] = __float2half(s * 1024.0f);
    }
}

// ======================= unified 1-pass fp16 mma GEMM ======================
// C = A @ B^T. Both operands single fp16, fp32 accum. Hoisted cp pointers.
// BM=BN=128, BK=32, 8 warps (64x32). 2 tiles/stage, double buffered (40KB).
#define MG_PITCH 80
#define MG_TILE  (128*MG_PITCH)       // 10240 B
#define MH_STG   (2*MG_TILE)          // 20480 B
#define MH_SMEM  (2*MH_STG)           // 40960 B

template<int MODE>
__global__ __launch_bounds__(256, 2)
void mma_fp16(const __half* __restrict__ A, const __half* __restrict__ Bm,
              float* __restrict__ C, const float* __restrict__ bias,
              int lda, int ldb, int kLen, int ldc, size_t sliceStride, float outScale){
    extern __shared__ __align__(16) char dsm[];
    const int tid  = threadIdx.x;
    const int wid  = tid >> 5, lane = tid & 31;
    const int m0   = blockIdx.x * 128;
    const int n0   = blockIdx.y * 128;
    const int kbase= blockIdx.z * kLen;
    const int wm   = (wid >> 2) * 64;
    const int wn   = (wid & 3) * 32;
    const uint32_t sbu = smem_u32(dsm);
    const int NIT = kLen >> 5;

    // hoisted per-thread load pointers (2 chunks per operand per tile)
    const int r0 = tid >> 2,         c0 = tid & 3;
    const int r1 = (tid+256) >> 2,   c1 = tid & 3;
    const __half* pA0 = A  + (size_t)(m0 + r0)*lda + kbase + c0*8;
    const __half* pA1 = A  + (size_t)(m0 + r1)*lda + kbase + c1*8;
    const __half* pB0 = Bm + (size_t)(n0 + r0)*ldb + kbase + c0*8;
    const __half* pB1 = Bm + (size_t)(n0 + r1)*ldb + kbase + c1*8;
    const uint32_t dA0 = r0*MG_PITCH + c0*16;
    const uint32_t dA1 = r1*MG_PITCH + c1*16;

    float acc[4][4][4];
    #pragma unroll
    for (int a=0;a<4;a++)
        #pragma unroll
        for (int b=0;b<4;b++)
            #pragma unroll
            for (int c=0;c<4;c++) acc[a][b][c] = 0.f;

    // issue stage 0
    {
        uint32_t base = sbu;
        cp16(base + dA0,           pA0);
        cp16(base + dA1,           pA1);
        cp16(base + MG_TILE + dA0, pB0);
        cp16(base + MG_TILE + dA1, pB1);
        cp_commit();
        pA0 += 32; pA1 += 32; pB0 += 32; pB1 += 32;
    }
    cp_wait0();
    __syncthreads();

    for (int t = 0; t < NIT; t++){
        int buf = t & 1;
        if (t + 1 < NIT){
            uint32_t base = sbu + (buf^1)*MH_STG;
            cp16(base + dA0,           pA0);
            cp16(base + dA1,           pA1);
            cp16(base + MG_TILE + dA0, pB0);
            cp16(base + MG_TILE + dA1, pB1);
            cp_commit();
            pA0 += 32; pA1 += 32; pB0 += 32; pB1 += 32;
        }

        const uint32_t sb = sbu + buf*MH_STG;
        #pragma unroll
        for (int ks = 0; ks < 2; ks++){
            uint32_t ah[4][4], bh[2][4];
            #pragma unroll
            for (int mb = 0; mb < 4; mb++){
                int row = wm + mb*16 + (lane & 15);
                ldsm4(ah[mb], sb + row*MG_PITCH + ks*32 + (lane >> 4)*16);
            }
            #pragma unroll
            for (int nb2 = 0; nb2 < 2; nb2++){
                int row = wn + nb2*16 + ((lane >> 3) & 1)*8 + (lane & 7);
                ldsm4(bh[nb2], sb + MG_TILE + row*MG_PITCH + ks*32 + (lane >> 4)*16);
            }
            #pragma unroll
            for (int mb = 0; mb < 4; mb++)
                #pragma unroll
                for (int nb = 0; nb < 4; nb++){
                    int nb2 = nb >> 1, odd = nb & 1;
                    mma16816h(acc[mb][nb], ah[mb], bh[nb2][odd?1:0], bh[nb2][odd?3:2]);
                }
        }

        if (t + 1 < NIT){ cp_wait0(); __syncthreads(); }
    }

    float* Co = (MODE == 2) ? (C + (size_t)blockIdx.z*sliceStride) : C;
    #pragma unroll
    for (int mb = 0; mb < 4; mb++){
        #pragma unroll
        for (int nb = 0; nb < 4; nb++){
            int r = m0 + wm + mb*16 + (lane >> 2);
            int c = n0 + wn + nb*8 + (lane & 3)*2;
            float2 v0 = make_float2(acc[mb][nb][0]*outScale, acc[mb][nb][1]*outScale);
            float2 v1 = make_float2(acc[mb][nb][2]*outScale, acc[mb][nb][3]*outScale);
            if (MODE == 0 && bias){
                float b0 = bias[c], b1 = bias[c+1];
                v0.x += b0; v0.y += b1;
                v1.x += b0; v1.y += b1;
            }
            *(float2*)&Co[(size_t)r*ldc + c]       = v0;
            *(float2*)&Co[(size_t)(r+8)*ldc + c]   = v1;
        }
    }
}

// ======================= final GEMM (A from zT via ldmatrix.trans) =========
// out[8192,1024] = z @ (Ct*1024)^T / 1024 + b_out, K=64 fully smem-resident.
// A loaded directly from zT [b*64+s][l] (coalesced), fragments via ldsm.trans.
#define FA_PITCH 136      // halves; 272B rows -> bank offset 4/row
#define FB_PITCH 72       // halves; 144B rows -> bank offset 4/row

__global__ __launch_bounds__(256, 2)
void mma_final(const float* __restrict__ bias, float* __restrict__ C){
    __shared__ __align__(16) __half SA[64*FA_PITCH];    // [s][l] tile
    __shared__ __align__(16) __half SB[128*FB_PITCH];   // [n][k] tile
    const int tid  = threadIdx.x;
    const int wid  = tid >> 5, lane = tid & 31;
    const int m0   = blockIdx.x * 128;
    const int n0   = blockIdx.y * 128;
    const int b    = m0 >> 11;
    const int l0   = m0 & (L_-1);
    const int wm   = (wid >> 2) * 64;
    const int wn   = (wid & 3) * 32;
    const uint32_t saU = smem_u32(SA);
    const uint32_t sbU = smem_u32(SB);

    // SA: 64 s-rows x 128 l halves = 16 chunks/row -> 1024 chunks
    #pragma unroll
    for (int it = 0; it < 4; it++){
        int i = tid + it*256;
        int r = i >> 4, c = i & 15;
        cp16(saU + r*(FA_PITCH*2) + c*16,
             g_zTf + (size_t)(b*DSTATE + r)*L_ + l0 + c*8);
    }
    // SB: 128 n-rows x 64 k halves = 8 chunks/row -> 1024 chunks
    #pragma unroll
    for (int it = 0; it < 4; it++){
        int i = tid + it*256;
        int r = i >> 3, c = i & 7;
        cp16(sbU + r*(FB_PITCH*2) + c*16,
             g_Ctf + (size_t)(n0 + r)*DSTATE + c*8);
    }
    cp_commit();
    cp_wait0();
    __syncthreads();

    float acc[4][4][4];
    #pragma unroll
    for (int a=0;a<4;a++)
        #pragma unroll
        for (int bb=0;bb<4;bb++)
            #pragma unroll
            for (int c=0;c<4;c++) acc[a][bb][c] = 0.f;

    const int g  = lane >> 3;       // 0..3 (ldsm.trans matrix index)
    const int r8 = lane & 7;
    #pragma unroll
    for (int ks = 0; ks < 4; ks++){          // K = 4 x 16
        uint32_t ah[4][4], bh[2][4];
        #pragma unroll
        for (int mb = 0; mb < 4; mb++){
            int srow = ks*16 + ((g & 2) << 2) + r8;       // +8 for g>=2
            int lcol = wm + mb*16 + (g & 1)*8;
            ldsm4t(ah[mb], saU + srow*(FA_PITCH*2) + lcol*2);
        }
        #pragma unroll
        for (int nb2 = 0; nb2 < 2; nb2++){
            int row = wn + nb2*16 + ((lane >> 3) & 1)*8 + (lane & 7);
            ldsm4(bh[nb2], sbU + row*(FB_PITCH*2) + ks*32 + (lane >> 4)*16);
        }
        #pragma unroll
        for (int mb = 0; mb < 4; mb++)
            #pragma unroll
            for (int nb = 0; nb < 4; nb++){
                int nb2 = nb >> 1, odd = nb & 1;
                mma16816h(acc[mb][nb], ah[mb], bh[nb2][odd?1:0], bh[nb2][odd?3:2]);
            }
    }

    const float outScale = 9.765625e-4f;    // 1/1024
    #pragma unroll
    for (int mb = 0; mb < 4; mb++){
        #pragma unroll
        for (int nb = 0; nb < 4; nb++){
            int r = m0 + wm + mb*16 + (lane >> 2);
            int c = n0 + wn + nb*8 + (lane & 3)*2;
            float b0 = bias[c], b1 = bias[c+1];
            float2 v0 = make_float2(acc[mb][nb][0]*outScale + b0, acc[mb][nb][1]*outScale + b1);
            float2 v1 = make_float2(acc[mb][nb][2]*outScale + b0, acc[mb][nb][3]*outScale + b1);
            *(float2*)&C[(size_t)r*DMODEL + c]     = v0;
            *(float2*)&C[(size_t)(r+8)*DMODEL + c] = v1;
        }
    }
}

// ======================= combine (descale + shift-sum + SSM param) =========
__global__ __launch_bounds__(256)
void combine(const float* __restrict__ A_log){
    const int tid = threadIdx.x;
    const int m0  = blockIdx.x * 64;
    __shared__ float sG[64*130];
    #pragma unroll
    for (int it = 0; it < 32; it++){
        int i = tid + it*256;
        int r = i >> 7, j = i & 127;
        int m = m0 + r, l = m & (L_-1);
        int lp = l < 3 ? l : 3;
        float sum = 0.f;
        int kmin = (l >= 3) ? 0 : (3 - l);
        #pragma unroll
        for (int k = 0; k < 4; k++)
            if (k >= kmin) sum += g_H4[(size_t)(m-3+k)*H4N + k*128 + j];
        sG[r*130 + j] = g_const[lp*NOUT + j] + sum*INV_ESCALE;
    }
    __syncthreads();
    #pragma unroll
    for (int it = 0; it < 16; it++){
        int p = tid + it*256;
        int s = p >> 6;
        int r = p & 63;
        float xs = sG[r*130 + s];
        float dv = sG[r*130 + 64 + s];
        float dt = dv > 20.f ? dv : log1pf(expf(dv));
        float Aa = -expf(A_log[s]);
        float dA = expf(Aa*dt);
        float dBx = (1.f - dA)/Aa * xs;
        int m = m0 + r;
        int b = m >> 11;
        int l = m & (L_-1);
        size_t o = ((size_t)(b*DSTATE + s))*L_ + l;
        g_dA[o]  = dA;
        g_dBx[o] = dBx;
    }
}

// ======================= scan (fp16 zT output) =============================
__global__ __launch_bounds__(256)
void scan_kernel(){
    const int bs = blockIdx.x;
    const int t  = threadIdx.x;
    const size_t base = (size_t)bs * L_;
    float a[8], bb[8];
    #pragma unroll
    for (int i=0;i<8;i++){ a[i] = g_dA[base + t*8 + i]; bb[i] = g_dBx[base + t*8 + i]; }

    float Ai = 1.f, Bi = 0.f;
    #pragma unroll
    for (int i=0;i<8;i++){ Bi = Bi*a[i] + bb[i]; Ai *= a[i]; }

    const unsigned lane = t & 31, wid = t >> 5;
    #pragma unroll
    for (int off = 1; off < 32; off <<= 1){
        float Au = __shfl_up_sync(0xffffffffu, Ai, off);
        float Bu = __shfl_up_sync(0xffffffffu, Bi, off);
        if (lane >= off){ Bi = Ai*Bu + Bi; Ai = Ai*Au; }
    }
    __shared__ float wA[8], wB[8], pB[8];
    if (lane == 31){ wA[wid] = Ai; wB[wid] = Bi; }
    __syncthreads();
    if (t == 0){
        float cB = 0.f;
        #pragma unroll
        for (int w = 0; w < 8; w++){
            pB[w] = cB;
            cB = cB*wA[w] + wB[w];
        }
    }
    __syncthreads();
    float eA = __shfl_up_sync(0xffffffffu, Ai, 1);
    float eB = __shfl_up_sync(0xffffffffu, Bi, 1);
    if (lane == 0){ eA = 1.f; eB = 0.f; }
    float z = eA*pB[wid] + eB;

    __half hb[8];
    #pragma unroll
    for (int i = 0; i < 8; i++){
        z = a[i]*z + bb[i];
        hb[i] = __float2half(z);
    }
    *(uint4*)&g_zTf[base + t*8] = *(uint4*)hb;
}

// ======================= launch ============================================
extern "C" void kernel_launch(void* const* d_in, const int* in_sizes, int n_in,
                              void* d_out, int out_size){
    const float* x      = (const float*)d_in[0];
    const float* W_in   = (const float*)d_in[1];
    const float* b_in   = (const float*)d_in[2];
    const float* conv_w = (const float*)d_in[3];
    const float* conv_b = (const float*)d_in[4];
    const float* W_x    = (const float*)d_in[5];
    const float* b_x    = (const float*)d_in[6];
    const float* W_dt   = (const float*)d_in[7];
    const float* b_dt   = (const float*)d_in[8];
    const float* A_log  = (const float*)d_in[9];
    const float* D_mat  = (const float*)d_in[10];
    const float* W_out  = (const float*)d_in[11];
    const float* b_out  = (const float*)d_in[12];
    float* out = (float*)d_out;

    cudaFuncSetAttribute(mma_fp16<0>, cudaFuncAttributeMaxDynamicSharedMemorySize, MH_SMEM);
    cudaFuncSetAttribute(mma_fp16<2>, cudaFuncAttributeMaxDynamicSharedMemorySize, MH_SMEM);

    float *pEp, *pH4;
    cudaGetSymbolAddress((void**)&pEp, g_Ep);
    cudaGetSymbolAddress((void**)&pH4, g_H4);
    __half *pAbf, *pWTf, *pEh, *pXh;
    cudaGetSymbolAddress((void**)&pAbf, g_Abf);
    cudaGetSymbolAddress((void**)&pWTf, g_WTf);
    cudaGetSymbolAddress((void**)&pEh,  g_Ehf);
    cudaGetSymbolAddress((void**)&pXh,  g_Xh);

    // 1. all independent prep + ct GEMM in one wave
    prep_all<<<PREP_BLOCKS, 256>>>(x, W_in, conv_w, conv_b,
                                   W_x, b_x, W_dt, b_dt, b_in, W_out, D_mat);

    // 2. E partials = (Abig*1024) @ (Win^T*1024)^T  (1-pass fp16, split-K=4)
    mma_fp16<2><<<dim3(H4N/128, DMODEL/128, ESPLIT), 256, MH_SMEM>>>(
        pAbf, pWTf, pEp, nullptr,
        DINNER, DINNER, DINNER/ESPLIT, DMODEL, (size_t)H4N*DMODEL, 1.0f);

    // 3. reduce_E (/256 -> E*4096 fp16) + reduce_ct (*1024 fp16)
    reduce_all<<<2048 + 256, 256>>>();

    // 4. H4 = fp16(X) @ (E*4096)^T  (1-pass fp16)
    mma_fp16<0><<<dim3(MTOT/128, H4N/128, 1), 256, MH_SMEM>>>(
        pXh, pEh, pH4, nullptr,
        DMODEL, DMODEL, DMODEL, H4N, 0, 1.0f);

    // 5-6. combine (descale), scan (fp16 zT)
    combine<<<MTOT/64, 256>>>(A_log);
    scan_kernel<<<B_*DSTATE, 256>>>();

    // 7. out = z @ (Ct*1024)^T / 1024 + b_out  (A from zT, ldsm.trans)
    mma_final<<<dim3(MTOT/128, DMODEL/128), 256>>>(b_out, out);
}